// round 9
// baseline (speedup 1.0000x reference)
#include <cuda_runtime.h>
#include <cuda_bf16.h>
#include <cstdint>
#include <cstddef>

#define N_NODES 100000
#define E_EDGES 1000000
#define D_DIM   64
#define NORM_INV 0.01f
#define LN_EPS  1e-5f

// Composite stacked weights: rows 0-63 Wlin, 64-127 Wu=A@Wlin, 128-191 Wv=B@Wlin
__device__ float g_Ws[192 * 64];
__device__ float g_bs[192];           // {blin, A@blin, B@blin}
// Per-node features for the edge kernel (bf16; att path is /100-damped)
__device__ __nv_bfloat16 g_uv[(size_t)N_NODES * 128];  // [node][0:64]=u, [64:128]=v
__device__ __nv_bfloat16 g_xc[(size_t)N_NODES * 64];   // x copy for scatter values
// Packed per-edge metadata {row, col, dist, emask} (16 B)
__device__ int4 g_ep[(size_t)E_EDGES];

// Exact sigmoid (used output-side in LN)
__device__ __forceinline__ float fsig(float v) {
    return __fdividef(1.0f, 1.0f + __expf(-v));
}
// Fast sigmoid via HW tanh (att path; /100-damped)
__device__ __forceinline__ float fsig_t(float v) {
    float t;
    asm("tanh.approx.f32 %0, %1;" : "=f"(t) : "f"(v * 0.5f));
    return fmaf(t, 0.5f, 0.5f);
}

__device__ __forceinline__ void red_add_v4(float* dst, float a, float b,
                                           float c, float d) {
    asm volatile("red.global.add.v4.f32 [%0], {%1, %2, %3, %4};"
                 :: "l"(dst), "f"(a), "f"(b), "f"(c), "f"(d) : "memory");
}

__device__ __forceinline__ float4 bf16x4_to_f4(uint2 r) {
    const float2 a = __bfloat1622float2(*reinterpret_cast<__nv_bfloat162*>(&r.x));
    const float2 b = __bfloat1622float2(*reinterpret_cast<__nv_bfloat162*>(&r.y));
    return make_float4(a.x, a.y, b.x, b.y);
}

// Packed f32x2 helpers (FFMA2 path — ptxas only emits FFMA2 from PTX f32x2)
#define FMA2(acc, a, b) \
    asm("fma.rn.f32x2 %0, %1, %2, %0;" : "+l"(acc) : "l"(a), "l"(b))

__device__ __forceinline__ unsigned long long packf2(float lo, float hi) {
    unsigned long long r;
    asm("mov.b64 %0, {%1, %2};" : "=l"(r) : "f"(lo), "f"(hi));
    return r;
}
__device__ __forceinline__ float2 unpackf2(unsigned long long v) {
    float lo, hi;
    asm("mov.b64 {%0, %1}, %2;" : "=f"(lo), "=f"(hi) : "l"(v));
    return make_float2(lo, hi);
}

// ---------------------------------------------------------------------------
// Kernel P (pack): g_ep[e] = {row, col, dist, emask}.
// ---------------------------------------------------------------------------
__global__ void pack_kernel(const int* __restrict__ edges,
                            const float* __restrict__ dist,
                            const float* __restrict__ emask)
{
    const int e = blockIdx.x * blockDim.x + threadIdx.x;
    if (e >= E_EDGES) return;
    int4 m;
    m.x = edges[e];
    m.y = edges[E_EDGES + e];
    m.z = __float_as_int(dist[e]);
    m.w = __float_as_int(emask[e]);
    g_ep[e] = m;
}

// ---------------------------------------------------------------------------
// Kernel 0 (compose): Wu = A@Wlin, Wv = B@Wlin, bu = A@blin, bv = B@blin.
// ---------------------------------------------------------------------------
__global__ void compose_kernel(const float* __restrict__ Wlin,
                               const float* __restrict__ blin,
                               const float* __restrict__ W1)
{
    __shared__ float sWlin[4096], sA[4096], sB[4096];
    const int tid = threadIdx.x;
    for (int i = tid; i < 4096; i += 256) {
        sWlin[i] = Wlin[i];
        const int r = i >> 6, c = i & 63;
        sA[i] = W1[r * 129 + c];
        sB[i] = W1[r * 129 + 64 + c];
    }
    __syncthreads();

    if (blockIdx.x == 0) {
        for (int i = tid; i < 4096; i += 256) g_Ws[i] = sWlin[i];
        if (tid < 64) {
            g_bs[tid] = blin[tid];
            float su = 0.f, sv = 0.f;
            for (int m = 0; m < 64; m++) {
                const float bm = __ldg(blin + m);
                su = fmaf(sA[tid * 64 + m], bm, su);
                sv = fmaf(sB[tid * 64 + m], bm, sv);
            }
            g_bs[64 + tid]  = su;
            g_bs[128 + tid] = sv;
        }
    }

    for (int idx = blockIdx.x * 256 + tid; idx < 4096; idx += gridDim.x * 256) {
        const int j = idx >> 6, k = idx & 63;
        float su = 0.f, sv = 0.f;
        #pragma unroll 8
        for (int m = 0; m < 64; m++) {
            const float w = sWlin[m * 64 + k];
            su = fmaf(sA[j * 64 + m], w, su);
            sv = fmaf(sB[j * 64 + m], w, sv);
        }
        g_Ws[4096 + idx] = su;
        g_Ws[8192 + idx] = sv;
    }
}

// ---------------------------------------------------------------------------
// Kernel 1 (prep): one stacked GEMM per node: {x,u,v} = Ws @ h + bs,
// computed with packed FFMA2 (f32x2).  Lane owns output pairs
// (j, j+32) for j = gg*64 + lane, gg = 0(x), 1(u), 2(v).
// Weights interleaved in smem as float2(W[j][k], W[j+32][k]) rows of 66;
// h staged duplicated as float2(h_k, h_k) -> both FFMA2 operands come
// straight from LDS.128, no register packing in the hot loop.
// ---------------------------------------------------------------------------
#define PREP_WI_F2   (3 * 32 * 66)            // interleaved weights, float2
#define PREP_SMEM    (PREP_WI_F2 * 8 + 192 * 4 + 8 * 8 * 64 * 8)  // 84,224 B

__global__ void __launch_bounds__(256, 2)
prep_kernel(const float* __restrict__ h,
            float* __restrict__ out_res)
{
    extern __shared__ float smem[];
    float2* sWi = (float2*)smem;                       // [3][32][66]
    float*  sbs = smem + PREP_WI_F2 * 2;               // 192
    float2* sHd = (float2*)(sbs + 192);                // [8 warps][8 e][64]

    const int tid = threadIdx.x;
    // Interleave weights: sWi[gg*32+r][k] = (W[gg*64+r][k], W[gg*64+r+32][k])
    for (int i = tid; i < 3 * 32 * 64; i += 256) {
        const int gg = i >> 11;
        const int r  = (i >> 6) & 31;
        const int k  = i & 63;
        const float lo = g_Ws[(gg * 64 + r) * 64 + k];
        const float hi = g_Ws[(gg * 64 + r + 32) * 64 + k];
        sWi[(gg * 32 + r) * 66 + k] = make_float2(lo, hi);
    }
    if (tid < 192) sbs[tid] = g_bs[tid];
    __syncthreads();

    const int lane = tid & 31;
    const int w    = tid >> 5;
    const int warpGlobal = blockIdx.x * 8 + w;
    const int nWarps     = gridDim.x * 8;

    const ulonglong2* wrow[3];
    unsigned long long binit[3];
    #pragma unroll
    for (int gg = 0; gg < 3; gg++) {
        wrow[gg]  = (const ulonglong2*)(sWi + (gg * 32 + lane) * 66);
        binit[gg] = packf2(sbs[gg * 64 + lane], sbs[gg * 64 + lane + 32]);
    }

    const float4* hf4 = (const float4*)h;
    float2* sHw = sHd + w * (8 * 64);

    for (int nb = warpGlobal * 8; nb < N_NODES; nb += nWarps * 8) {
        // Stage 8 h rows, duplicated per element (2 nodes per half-warp)
        #pragma unroll
        for (int ep = 0; ep < 8; ep += 2) {
            const int e  = ep + (lane >> 4);
            const int li = lane & 15;
            const float4 h4 = hf4[(size_t)(nb + e) * 16 + li];
            float2* dst = sHw + e * 64 + 4 * li;
            dst[0] = make_float2(h4.x, h4.x);
            dst[1] = make_float2(h4.y, h4.y);
            dst[2] = make_float2(h4.z, h4.z);
            dst[3] = make_float2(h4.w, h4.w);
        }
        __syncwarp();

        unsigned long long acc[3][8];
        #pragma unroll
        for (int gg = 0; gg < 3; gg++)
            #pragma unroll
            for (int e = 0; e < 8; e++) acc[gg][e] = binit[gg];

        #pragma unroll 4
        for (int kk = 0; kk < 32; kk++) {       // 2 k-steps per kk
            ulonglong2 wv[3];
            #pragma unroll
            for (int gg = 0; gg < 3; gg++) wv[gg] = wrow[gg][kk];
            #pragma unroll
            for (int e = 0; e < 8; e++) {
                const ulonglong2 xv =
                    ((const ulonglong2*)(sHw + e * 64))[kk];  // broadcast
                #pragma unroll
                for (int gg = 0; gg < 3; gg++) {
                    FMA2(acc[gg][e], wv[gg].x, xv.x);
                    FMA2(acc[gg][e], wv[gg].y, xv.y);
                }
            }
        }

        #pragma unroll
        for (int e = 0; e < 8; e++) {
            const size_t n64  = (size_t)(nb + e) * 64;
            const size_t n128 = (size_t)(nb + e) * 128;
            const float2 xo = unpackf2(acc[0][e]);
            const float2 uo = unpackf2(acc[1][e]);
            const float2 vo = unpackf2(acc[2][e]);
            out_res[n64 + lane]      = xo.x;
            out_res[n64 + lane + 32] = xo.y;
            g_xc[n64 + lane]       = __float2bfloat16(xo.x);
            g_xc[n64 + lane + 32]  = __float2bfloat16(xo.y);
            g_uv[n128 + lane]      = __float2bfloat16(uo.x);
            g_uv[n128 + lane + 32] = __float2bfloat16(uo.y);
            g_uv[n128 + 64 + lane]      = __float2bfloat16(vo.x);
            g_uv[n128 + 64 + lane + 32] = __float2bfloat16(vo.y);
        }
        __syncwarp();
    }
}

// ---------------------------------------------------------------------------
// Kernel 2 (edge): t = u[row]+v[col]+wd*d+b1; att = sig(W2.silu(t)+b2);
// fp32 red.global.add.v4 of att*x_col into d_out[row].
// ---------------------------------------------------------------------------
__global__ void edge_kernel(const float* __restrict__ W1,   // [64][129]
                            const float* __restrict__ b1,
                            const float* __restrict__ W2,   // [64]
                            const float* __restrict__ b2p,
                            float* __restrict__ agg)        // d_out
{
    const int lane = threadIdx.x & 31;
    const int w    = threadIdx.x >> 5;
    const int hw   = lane >> 4;      // which edge of the pair
    const int li   = lane & 15;      // dim group within edge

    const float4 w2_4 = ((const float4*)W2)[li];
    const float4 b1_4 = ((const float4*)b1)[li];
    float4 wd_4;
    wd_4.x = __ldg(W1 + (size_t)(li * 4 + 0) * 129 + 128);
    wd_4.y = __ldg(W1 + (size_t)(li * 4 + 1) * 129 + 128);
    wd_4.z = __ldg(W1 + (size_t)(li * 4 + 2) * 129 + 128);
    wd_4.w = __ldg(W1 + (size_t)(li * 4 + 3) * 129 + 128);
    const float b2 = b2p[0];

    const uint2* uvp = (const uint2*)g_uv;   // 32 uint2 per node (u:0-15, v:16-31)
    const uint2* xcp = (const uint2*)g_xc;   // 16 uint2 per node

    const int warpGlobal = blockIdx.x * 8 + w;
    const int nWarps     = gridDim.x * 8;

    for (int eb = warpGlobal * 4; eb < E_EDGES; eb += nWarps * 4) {
        int4 m[2];
        m[0] = __ldg(g_ep + eb + hw);
        m[1] = __ldg(g_ep + eb + 2 + hw);

        uint2 ur[2], vr[2], xr[2];
        #pragma unroll
        for (int s = 0; s < 2; s++) {
            ur[s] = __ldg(uvp + (size_t)m[s].x * 32 + li);
            vr[s] = __ldg(uvp + (size_t)m[s].y * 32 + 16 + li);
            xr[s] = __ldg(xcp + (size_t)m[s].y * 16 + li);
        }

        #pragma unroll
        for (int s = 0; s < 2; s++) {
            const float d  = __int_as_float(m[s].z);
            const float em = __int_as_float(m[s].w);
            const float4 u4 = bf16x4_to_f4(ur[s]);
            const float4 v4 = bf16x4_to_f4(vr[s]);
            const float4 x4 = bf16x4_to_f4(xr[s]);

            float4 t;
            t.x = fmaf(d, wd_4.x, u4.x + v4.x + b1_4.x);
            t.y = fmaf(d, wd_4.y, u4.y + v4.y + b1_4.y);
            t.z = fmaf(d, wd_4.z, u4.z + v4.z + b1_4.z);
            t.w = fmaf(d, wd_4.w, u4.w + v4.w + b1_4.w);

            const float h0 = t.x * fsig_t(t.x);
            const float h1 = t.y * fsig_t(t.y);
            const float h2 = t.z * fsig_t(t.z);
            const float h3 = t.w * fsig_t(t.w);

            float p = fmaf(h0, w2_4.x,
                      fmaf(h1, w2_4.y,
                      fmaf(h2, w2_4.z, h3 * w2_4.w)));
            #pragma unroll
            for (int off = 8; off; off >>= 1)
                p += __shfl_xor_sync(0xffffffffu, p, off);

            const float att = fsig_t(p + b2) * em * NORM_INV;

            float* dst = agg + (size_t)m[s].x * 64 + li * 4;
            red_add_v4(dst, x4.x * att, x4.y * att, x4.z * att, x4.w * att);
        }
    }
}

// ---------------------------------------------------------------------------
// Kernel 3: out = silu(LN(io)).  io holds x + agg (fp32).
// ---------------------------------------------------------------------------
__global__ void ln_kernel(const float* __restrict__ g,
                          const float* __restrict__ bln,
                          float* __restrict__ io)
{
    const int lane = threadIdx.x & 31;
    const int w    = threadIdx.x >> 5;
    const int li   = lane & 15;
    const int row  = blockIdx.x * 16 + w * 2 + (lane >> 4);
    if (row >= N_NODES) return;

    float4 v = ((const float4*)io)[(size_t)row * 16 + li];

    float s = v.x + v.y + v.z + v.w;
    #pragma unroll
    for (int off = 8; off; off >>= 1)
        s += __shfl_xor_sync(0xffffffffu, s, off);
    const float mu = s * (1.0f / 64.0f);

    const float dx = v.x - mu, dy = v.y - mu, dz = v.z - mu, dw = v.w - mu;
    float q = dx * dx + dy * dy + dz * dz + dw * dw;
    #pragma unroll
    for (int off = 8; off; off >>= 1)
        q += __shfl_xor_sync(0xffffffffu, q, off);
    const float rs = rsqrtf(q * (1.0f / 64.0f) + LN_EPS);

    const float4 gg = __ldg((const float4*)g + li);
    const float4 bb = __ldg((const float4*)bln + li);
    float4 o;
    o.x = fmaf(dx * rs, gg.x, bb.x);
    o.y = fmaf(dy * rs, gg.y, bb.y);
    o.z = fmaf(dz * rs, gg.z, bb.z);
    o.w = fmaf(dw * rs, gg.w, bb.w);
    o.x *= fsig(o.x);
    o.y *= fsig(o.y);
    o.z *= fsig(o.z);
    o.w *= fsig(o.w);
    ((float4*)io)[(size_t)row * 16 + li] = o;
}

// ---------------------------------------------------------------------------
// Launch: pack -> compose -> prep -> edge -> layernorm.
// ---------------------------------------------------------------------------
extern "C" void kernel_launch(void* const* d_in, const int* in_sizes, int n_in,
                              void* d_out, int out_size)
{
    const float* h     = (const float*)d_in[0];
    const float* dist  = (const float*)d_in[1];
    const int*   edges = (const int*)d_in[2];   // JAX x64-disabled => int32
    /* d_in[3] node_mask: unused by the reference */
    const float* emask = (const float*)d_in[4];
    const float* Wlin  = (const float*)d_in[5];
    const float* blin  = (const float*)d_in[6];
    const float* W1    = (const float*)d_in[7];
    const float* b1    = (const float*)d_in[8];
    const float* W2    = (const float*)d_in[9];
    const float* b2    = (const float*)d_in[10];
    const float* lng   = (const float*)d_in[11];
    const float* lnb   = (const float*)d_in[12];
    float* out = (float*)d_out;

    cudaFuncSetAttribute(prep_kernel,
                         cudaFuncAttributeMaxDynamicSharedMemorySize, PREP_SMEM);

    pack_kernel<<<(E_EDGES + 511) / 512, 512>>>(edges, dist, emask);
    compose_kernel<<<16, 256>>>(Wlin, blin, W1);
    prep_kernel<<<592, 256, PREP_SMEM>>>(h, out);
    edge_kernel<<<740, 256>>>(W1, b1, W2, b2, out);      // 5 blocks/SM, 1 wave
    ln_kernel<<<(N_NODES + 15) / 16, 256>>>(lng, lnb, out);
}

// round 10
// speedup vs baseline: 1.0300x; 1.0300x over previous
#include <cuda_runtime.h>
#include <cuda_bf16.h>
#include <cstdint>
#include <cstddef>

#define N_NODES 100000
#define E_EDGES 1000000
#define D_DIM   64
#define NORM_INV 0.01f
#define LN_EPS  1e-5f

// Composite stacked weights: rows 0-63 Wlin, 64-127 Wu=A@Wlin, 128-191 Wv=B@Wlin
__device__ float g_Ws[192 * 64];
__device__ float g_bs[192];           // {blin, A@blin, B@blin}
// Per-node features for the edge kernel (bf16; att path is /100-damped)
__device__ __nv_bfloat16 g_uv[(size_t)N_NODES * 128];  // [node][0:64]=u, [64:128]=v
__device__ __nv_bfloat16 g_xc[(size_t)N_NODES * 64];   // x copy for scatter values
// Packed per-edge metadata {row, col, dist, emask} (16 B)
__device__ int4 g_ep[(size_t)E_EDGES];

// Exact sigmoid (used output-side in LN)
__device__ __forceinline__ float fsig(float v) {
    return __fdividef(1.0f, 1.0f + __expf(-v));
}
// Fast sigmoid via HW tanh (att path; /100-damped)
__device__ __forceinline__ float fsig_t(float v) {
    float t;
    asm("tanh.approx.f32 %0, %1;" : "=f"(t) : "f"(v * 0.5f));
    return fmaf(t, 0.5f, 0.5f);
}

__device__ __forceinline__ void red_add_v4(float* dst, float a, float b,
                                           float c, float d) {
    asm volatile("red.global.add.v4.f32 [%0], {%1, %2, %3, %4};"
                 :: "l"(dst), "f"(a), "f"(b), "f"(c), "f"(d) : "memory");
}

__device__ __forceinline__ float4 bf16x4_to_f4(uint2 r) {
    const float2 a = __bfloat1622float2(*reinterpret_cast<__nv_bfloat162*>(&r.x));
    const float2 b = __bfloat1622float2(*reinterpret_cast<__nv_bfloat162*>(&r.y));
    return make_float4(a.x, a.y, b.x, b.y);
}

// ---------------------------------------------------------------------------
// Kernel 0 (compose): Wu = A@Wlin, Wv = B@Wlin, bu = A@blin, bv = B@blin.
// ---------------------------------------------------------------------------
__global__ void compose_kernel(const float* __restrict__ Wlin,
                               const float* __restrict__ blin,
                               const float* __restrict__ W1)
{
    __shared__ float sWlin[4096], sA[4096], sB[4096];
    const int tid = threadIdx.x;
    for (int i = tid; i < 4096; i += 256) {
        sWlin[i] = Wlin[i];
        const int r = i >> 6, c = i & 63;
        sA[i] = W1[r * 129 + c];
        sB[i] = W1[r * 129 + 64 + c];
    }
    __syncthreads();

    if (blockIdx.x == 0) {
        for (int i = tid; i < 4096; i += 256) g_Ws[i] = sWlin[i];
        if (tid < 64) {
            g_bs[tid] = blin[tid];
            float su = 0.f, sv = 0.f;
            for (int m = 0; m < 64; m++) {
                const float bm = __ldg(blin + m);
                su = fmaf(sA[tid * 64 + m], bm, su);
                sv = fmaf(sB[tid * 64 + m], bm, sv);
            }
            g_bs[64 + tid]  = su;
            g_bs[128 + tid] = sv;
        }
    }

    for (int idx = blockIdx.x * 256 + tid; idx < 4096; idx += gridDim.x * 256) {
        const int j = idx >> 6, k = idx & 63;
        float su = 0.f, sv = 0.f;
        #pragma unroll 8
        for (int m = 0; m < 64; m++) {
            const float w = sWlin[m * 64 + k];
            su = fmaf(sA[j * 64 + m], w, su);
            sv = fmaf(sB[j * 64 + m], w, sv);
        }
        g_Ws[4096 + idx] = su;
        g_Ws[8192 + idx] = sv;
    }
}

// ---------------------------------------------------------------------------
// Kernel 1 (prep): edge-metadata pack (grid-stride prologue, hides under
// the FFMA-bound GEMM) + one stacked GEMM per node: {x,u,v} = Ws @ h + bs.
// 8 nodes per warp-iteration; lane owns 6 outputs j = lane + 32g.
// ---------------------------------------------------------------------------
#define PREP_SMEM ((192 * 68 + 192) * 4 + 8 * 8 * 64 * 4)   // 69,376 B

__global__ void __launch_bounds__(256, 2)
prep_kernel(const float* __restrict__ h,
            const int* __restrict__ edges,
            const float* __restrict__ dist,
            const float* __restrict__ emask,
            float* __restrict__ out_res)
{
    extern __shared__ float smem[];
    float*  sWs = smem;                    // 192*68
    float*  sbs = sWs + 192 * 68;          // 192
    float4* sH  = (float4*)(sbs + 192);    // [8 warps][8 nodes][16 f4]

    const int tid = threadIdx.x;

    // --- Pack prologue: g_ep[e] = {row, col, dist, emask}.  Pure-memory
    // work that overlaps the FFMA-bound GEMM below across the grid.
    {
        const int nThreads = gridDim.x * 256;
        for (int e = blockIdx.x * 256 + tid; e < E_EDGES; e += nThreads) {
            int4 m;
            m.x = __ldg(edges + e);
            m.y = __ldg(edges + E_EDGES + e);
            m.z = __float_as_int(__ldg(dist + e));
            m.w = __float_as_int(__ldg(emask + e));
            g_ep[e] = m;
        }
    }

    for (int i = tid; i < 192 * 64; i += 256)
        sWs[(i >> 6) * 68 + (i & 63)] = g_Ws[i];
    if (tid < 192) sbs[tid] = g_bs[tid];
    __syncthreads();

    const int lane = tid & 31;
    const int w    = tid >> 5;
    const int warpGlobal = blockIdx.x * 8 + w;
    const int nWarps     = gridDim.x * 8;

    const float4* wp[6];
    float bj[6];
    #pragma unroll
    for (int g = 0; g < 6; g++) {
        wp[g] = ((const float4*)sWs) + (g * 32 + lane) * 17;
        bj[g] = sbs[g * 32 + lane];
    }
    const float4* hf4 = (const float4*)h;
    float4* sHw = sH + w * (8 * 16);

    for (int nb = warpGlobal * 8; nb < N_NODES; nb += nWarps * 8) {
        #pragma unroll
        for (int ep = 0; ep < 8; ep += 2) {
            const int e  = ep + (lane >> 4);
            const int li = lane & 15;
            sHw[e * 16 + li] = hf4[(size_t)(nb + e) * 16 + li];
        }
        __syncwarp();

        float acc[6][8];
        #pragma unroll
        for (int g = 0; g < 6; g++)
            #pragma unroll
            for (int e = 0; e < 8; e++) acc[g][e] = bj[g];

        #pragma unroll 2
        for (int kk = 0; kk < 16; kk++) {
            float4 wr[6];
            #pragma unroll
            for (int g = 0; g < 6; g++) wr[g] = wp[g][kk];
            #pragma unroll
            for (int e = 0; e < 8; e++) {
                const float4 xv = sHw[e * 16 + kk];   // warp-uniform broadcast
                #pragma unroll
                for (int g = 0; g < 6; g++) {
                    acc[g][e] = fmaf(wr[g].x, xv.x, acc[g][e]);
                    acc[g][e] = fmaf(wr[g].y, xv.y, acc[g][e]);
                    acc[g][e] = fmaf(wr[g].z, xv.z, acc[g][e]);
                    acc[g][e] = fmaf(wr[g].w, xv.w, acc[g][e]);
                }
            }
        }

        #pragma unroll
        for (int e = 0; e < 8; e++) {
            const size_t n64  = (size_t)(nb + e) * 64;
            const size_t n128 = (size_t)(nb + e) * 128;
            out_res[n64 + lane]      = acc[0][e];
            out_res[n64 + lane + 32] = acc[1][e];
            g_xc[n64 + lane]       = __float2bfloat16(acc[0][e]);
            g_xc[n64 + lane + 32]  = __float2bfloat16(acc[1][e]);
            g_uv[n128 + lane]      = __float2bfloat16(acc[2][e]);
            g_uv[n128 + lane + 32] = __float2bfloat16(acc[3][e]);
            g_uv[n128 + 64 + lane]      = __float2bfloat16(acc[4][e]);
            g_uv[n128 + 64 + lane + 32] = __float2bfloat16(acc[5][e]);
        }
        __syncwarp();
    }
}

// ---------------------------------------------------------------------------
// Kernel 2 (edge): t = u[row]+v[col]+wd*d+b1; att = sig(W2.silu(t)+b2);
// fp32 red.global.add.v4 of att*x_col into d_out[row].
// 4 edges per warp-iter; all gathers batched up front for MLP.
// ---------------------------------------------------------------------------
__global__ void edge_kernel(const float* __restrict__ W1,   // [64][129]
                            const float* __restrict__ b1,
                            const float* __restrict__ W2,   // [64]
                            const float* __restrict__ b2p,
                            float* __restrict__ agg)        // d_out
{
    const int lane = threadIdx.x & 31;
    const int w    = threadIdx.x >> 5;
    const int hw   = lane >> 4;      // which edge of the pair
    const int li   = lane & 15;      // dim group within edge

    const float4 w2_4 = ((const float4*)W2)[li];
    const float4 b1_4 = ((const float4*)b1)[li];
    float4 wd_4;
    wd_4.x = __ldg(W1 + (size_t)(li * 4 + 0) * 129 + 128);
    wd_4.y = __ldg(W1 + (size_t)(li * 4 + 1) * 129 + 128);
    wd_4.z = __ldg(W1 + (size_t)(li * 4 + 2) * 129 + 128);
    wd_4.w = __ldg(W1 + (size_t)(li * 4 + 3) * 129 + 128);
    const float b2 = b2p[0];

    const uint2* uvp = (const uint2*)g_uv;   // 32 uint2 per node (u:0-15, v:16-31)
    const uint2* xcp = (const uint2*)g_xc;   // 16 uint2 per node

    const int warpGlobal = blockIdx.x * 8 + w;
    const int nWarps     = gridDim.x * 8;

    for (int eb = warpGlobal * 4; eb < E_EDGES; eb += nWarps * 4) {
        // Batch metadata + gathers for both s-steps (independent chains)
        int4 m[2];
        m[0] = __ldg(g_ep + eb + hw);
        m[1] = __ldg(g_ep + eb + 2 + hw);

        uint2 ur[2], vr[2], xr[2];
        #pragma unroll
        for (int s = 0; s < 2; s++) {
            ur[s] = __ldg(uvp + (size_t)m[s].x * 32 + li);
            vr[s] = __ldg(uvp + (size_t)m[s].y * 32 + 16 + li);
            xr[s] = __ldg(xcp + (size_t)m[s].y * 16 + li);
        }

        #pragma unroll
        for (int s = 0; s < 2; s++) {
            const float d  = __int_as_float(m[s].z);
            const float em = __int_as_float(m[s].w);
            const float4 u4 = bf16x4_to_f4(ur[s]);
            const float4 v4 = bf16x4_to_f4(vr[s]);
            const float4 x4 = bf16x4_to_f4(xr[s]);

            float4 t;
            t.x = fmaf(d, wd_4.x, u4.x + v4.x + b1_4.x);
            t.y = fmaf(d, wd_4.y, u4.y + v4.y + b1_4.y);
            t.z = fmaf(d, wd_4.z, u4.z + v4.z + b1_4.z);
            t.w = fmaf(d, wd_4.w, u4.w + v4.w + b1_4.w);

            const float h0 = t.x * fsig_t(t.x);
            const float h1 = t.y * fsig_t(t.y);
            const float h2 = t.z * fsig_t(t.z);
            const float h3 = t.w * fsig_t(t.w);

            float p = fmaf(h0, w2_4.x,
                      fmaf(h1, w2_4.y,
                      fmaf(h2, w2_4.z, h3 * w2_4.w)));
            #pragma unroll
            for (int off = 8; off; off >>= 1)          // reduce within 16 lanes
                p += __shfl_xor_sync(0xffffffffu, p, off);

            const float att = fsig_t(p + b2) * em * NORM_INV;

            float* dst = agg + (size_t)m[s].x * 64 + li * 4;
            red_add_v4(dst, x4.x * att, x4.y * att, x4.z * att, x4.w * att);
        }
    }
}

// ---------------------------------------------------------------------------
// Kernel 3: out = silu(LN(io)).  io holds x + agg (fp32).
// 16 lanes per row (float4 per lane), 2 rows per warp. Exact sigmoid.
// ---------------------------------------------------------------------------
__global__ void ln_kernel(const float* __restrict__ g,
                          const float* __restrict__ bln,
                          float* __restrict__ io)
{
    const int lane = threadIdx.x & 31;
    const int w    = threadIdx.x >> 5;
    const int li   = lane & 15;
    const int row  = blockIdx.x * 16 + w * 2 + (lane >> 4);
    if (row >= N_NODES) return;

    float4 v = ((const float4*)io)[(size_t)row * 16 + li];

    float s = v.x + v.y + v.z + v.w;
    #pragma unroll
    for (int off = 8; off; off >>= 1)
        s += __shfl_xor_sync(0xffffffffu, s, off);
    const float mu = s * (1.0f / 64.0f);

    const float dx = v.x - mu, dy = v.y - mu, dz = v.z - mu, dw = v.w - mu;
    float q = dx * dx + dy * dy + dz * dz + dw * dw;
    #pragma unroll
    for (int off = 8; off; off >>= 1)
        q += __shfl_xor_sync(0xffffffffu, q, off);
    const float rs = rsqrtf(q * (1.0f / 64.0f) + LN_EPS);

    const float4 gg = __ldg((const float4*)g + li);
    const float4 bb = __ldg((const float4*)bln + li);
    float4 o;
    o.x = fmaf(dx * rs, gg.x, bb.x);
    o.y = fmaf(dy * rs, gg.y, bb.y);
    o.z = fmaf(dz * rs, gg.z, bb.z);
    o.w = fmaf(dw * rs, gg.w, bb.w);
    o.x *= fsig(o.x);
    o.y *= fsig(o.y);
    o.z *= fsig(o.z);
    o.w *= fsig(o.w);
    ((float4*)io)[(size_t)row * 16 + li] = o;
}

// ---------------------------------------------------------------------------
// Launch: compose -> prep(+pack) -> edge -> layernorm.
// ---------------------------------------------------------------------------
extern "C" void kernel_launch(void* const* d_in, const int* in_sizes, int n_in,
                              void* d_out, int out_size)
{
    const float* h     = (const float*)d_in[0];
    const float* dist  = (const float*)d_in[1];
    const int*   edges = (const int*)d_in[2];   // JAX x64-disabled => int32
    /* d_in[3] node_mask: unused by the reference */
    const float* emask = (const float*)d_in[4];
    const float* Wlin  = (const float*)d_in[5];
    const float* blin  = (const float*)d_in[6];
    const float* W1    = (const float*)d_in[7];
    const float* b1    = (const float*)d_in[8];
    const float* W2    = (const float*)d_in[9];
    const float* b2    = (const float*)d_in[10];
    const float* lng   = (const float*)d_in[11];
    const float* lnb   = (const float*)d_in[12];
    float* out = (float*)d_out;

    cudaFuncSetAttribute(prep_kernel,
                         cudaFuncAttributeMaxDynamicSharedMemorySize, PREP_SMEM);

    compose_kernel<<<16, 256>>>(Wlin, blin, W1);
    prep_kernel<<<592, 256, PREP_SMEM>>>(h, edges, dist, emask, out);
    edge_kernel<<<740, 256>>>(W1, b1, W2, b2, out);      // 5 blocks/SM, 1 wave
    ln_kernel<<<(N_NODES + 15) / 16, 256>>>(lng, lnb, out);
}

// round 11
// speedup vs baseline: 1.0497x; 1.0191x over previous
#include <cuda_runtime.h>
#include <cuda_bf16.h>
#include <cstdint>
#include <cstddef>

#define N_NODES 100000
#define E_EDGES 1000000
#define D_DIM   64
#define NORM_INV 0.01f
#define LN_EPS  1e-5f

// Composite stacked weights: rows 0-63 Wlin, 64-127 Wu=A@Wlin, 128-191 Wv=B@Wlin
__device__ float g_Ws[192 * 64];
__device__ float g_bs[192];           // {blin, A@blin, B@blin}
// Per-node features for the edge kernel (bf16; att path is /100-damped)
__device__ __nv_bfloat16 g_uv[(size_t)N_NODES * 128];  // [node][0:64]=u, [64:128]=v
__device__ __nv_bfloat16 g_xc[(size_t)N_NODES * 64];   // x copy for scatter values
// Packed per-edge metadata {row, col, dist, emask} (16 B)
__device__ int4 g_ep[(size_t)E_EDGES];

// Exact sigmoid (used output-side in LN)
__device__ __forceinline__ float fsig(float v) {
    return __fdividef(1.0f, 1.0f + __expf(-v));
}
// Fast sigmoid via HW tanh (att path; /100-damped)
__device__ __forceinline__ float fsig_t(float v) {
    float t;
    asm("tanh.approx.f32 %0, %1;" : "=f"(t) : "f"(v * 0.5f));
    return fmaf(t, 0.5f, 0.5f);
}

__device__ __forceinline__ void red_add_v4(float* dst, float a, float b,
                                           float c, float d) {
    asm volatile("red.global.add.v4.f32 [%0], {%1, %2, %3, %4};"
                 :: "l"(dst), "f"(a), "f"(b), "f"(c), "f"(d) : "memory");
}

__device__ __forceinline__ float4 bf16x4_to_f4(uint2 r) {
    const float2 a = __bfloat1622float2(*reinterpret_cast<__nv_bfloat162*>(&r.x));
    const float2 b = __bfloat1622float2(*reinterpret_cast<__nv_bfloat162*>(&r.y));
    return make_float4(a.x, a.y, b.x, b.y);
}

// ---------------------------------------------------------------------------
// Kernel 0 (setup): block-specialized.
//   blocks 0-15 : compose Wu = A@Wlin, Wv = B@Wlin, bu/bv (and copy Wlin).
//   all blocks  : grid-stride pack g_ep[e] = {row, col, dist, emask}.
// The two workloads run in parallel across blocks of one small kernel.
// ---------------------------------------------------------------------------
__global__ void setup_kernel(const float* __restrict__ Wlin,
                             const float* __restrict__ blin,
                             const float* __restrict__ W1,
                             const int* __restrict__ edges,
                             const float* __restrict__ dist,
                             const float* __restrict__ emask)
{
    __shared__ float sWlin[4096], sA[4096], sB[4096];
    const int tid = threadIdx.x;

    if (blockIdx.x < 16) {
        for (int i = tid; i < 4096; i += 256) {
            sWlin[i] = Wlin[i];
            const int r = i >> 6, c = i & 63;
            sA[i] = W1[r * 129 + c];
            sB[i] = W1[r * 129 + 64 + c];
        }
        __syncthreads();

        if (blockIdx.x == 0) {
            for (int i = tid; i < 4096; i += 256) g_Ws[i] = sWlin[i];
            if (tid < 64) {
                g_bs[tid] = blin[tid];
                float su = 0.f, sv = 0.f;
                for (int m = 0; m < 64; m++) {
                    const float bm = __ldg(blin + m);
                    su = fmaf(sA[tid * 64 + m], bm, su);
                    sv = fmaf(sB[tid * 64 + m], bm, sv);
                }
                g_bs[64 + tid]  = su;
                g_bs[128 + tid] = sv;
            }
        }

        for (int idx = blockIdx.x * 256 + tid; idx < 4096; idx += 16 * 256) {
            const int j = idx >> 6, k = idx & 63;
            float su = 0.f, sv = 0.f;
            #pragma unroll 8
            for (int m = 0; m < 64; m++) {
                const float w = sWlin[m * 64 + k];
                su = fmaf(sA[j * 64 + m], w, su);
                sv = fmaf(sB[j * 64 + m], w, sv);
            }
            g_Ws[4096 + idx] = su;
            g_Ws[8192 + idx] = sv;
        }
    }

    // Pack (all blocks)
    const int nThreads = gridDim.x * 256;
    for (int e = blockIdx.x * 256 + tid; e < E_EDGES; e += nThreads) {
        int4 m;
        m.x = __ldg(edges + e);
        m.y = __ldg(edges + E_EDGES + e);
        m.z = __float_as_int(__ldg(dist + e));
        m.w = __float_as_int(__ldg(emask + e));
        g_ep[e] = m;
    }
}

// ---------------------------------------------------------------------------
// Kernel 1 (prep): one stacked GEMM per node: {x,u,v} = Ws @ h + bs.
// 8 nodes per warp-iteration; lane owns 6 outputs j = lane + 32g.
// ---------------------------------------------------------------------------
#define PREP_SMEM ((192 * 68 + 192) * 4 + 8 * 8 * 64 * 4)   // 69,376 B

__global__ void __launch_bounds__(256, 2)
prep_kernel(const float* __restrict__ h,
            float* __restrict__ out_res)
{
    extern __shared__ float smem[];
    float*  sWs = smem;                    // 192*68
    float*  sbs = sWs + 192 * 68;          // 192
    float4* sH  = (float4*)(sbs + 192);    // [8 warps][8 nodes][16 f4]

    const int tid = threadIdx.x;
    for (int i = tid; i < 192 * 64; i += 256)
        sWs[(i >> 6) * 68 + (i & 63)] = g_Ws[i];
    if (tid < 192) sbs[tid] = g_bs[tid];
    __syncthreads();

    const int lane = tid & 31;
    const int w    = tid >> 5;
    const int warpGlobal = blockIdx.x * 8 + w;
    const int nWarps     = gridDim.x * 8;

    const float4* wp[6];
    float bj[6];
    #pragma unroll
    for (int g = 0; g < 6; g++) {
        wp[g] = ((const float4*)sWs) + (g * 32 + lane) * 17;
        bj[g] = sbs[g * 32 + lane];
    }
    const float4* hf4 = (const float4*)h;
    float4* sHw = sH + w * (8 * 16);

    for (int nb = warpGlobal * 8; nb < N_NODES; nb += nWarps * 8) {
        #pragma unroll
        for (int ep = 0; ep < 8; ep += 2) {
            const int e  = ep + (lane >> 4);
            const int li = lane & 15;
            sHw[e * 16 + li] = hf4[(size_t)(nb + e) * 16 + li];
        }
        __syncwarp();

        float acc[6][8];
        #pragma unroll
        for (int g = 0; g < 6; g++)
            #pragma unroll
            for (int e = 0; e < 8; e++) acc[g][e] = bj[g];

        #pragma unroll 2
        for (int kk = 0; kk < 16; kk++) {
            float4 wr[6];
            #pragma unroll
            for (int g = 0; g < 6; g++) wr[g] = wp[g][kk];
            #pragma unroll
            for (int e = 0; e < 8; e++) {
                const float4 xv = sHw[e * 16 + kk];   // warp-uniform broadcast
                #pragma unroll
                for (int g = 0; g < 6; g++) {
                    acc[g][e] = fmaf(wr[g].x, xv.x, acc[g][e]);
                    acc[g][e] = fmaf(wr[g].y, xv.y, acc[g][e]);
                    acc[g][e] = fmaf(wr[g].z, xv.z, acc[g][e]);
                    acc[g][e] = fmaf(wr[g].w, xv.w, acc[g][e]);
                }
            }
        }

        #pragma unroll
        for (int e = 0; e < 8; e++) {
            const size_t n64  = (size_t)(nb + e) * 64;
            const size_t n128 = (size_t)(nb + e) * 128;
            out_res[n64 + lane]      = acc[0][e];
            out_res[n64 + lane + 32] = acc[1][e];
            g_xc[n64 + lane]       = __float2bfloat16(acc[0][e]);
            g_xc[n64 + lane + 32]  = __float2bfloat16(acc[1][e]);
            g_uv[n128 + lane]      = __float2bfloat16(acc[2][e]);
            g_uv[n128 + lane + 32] = __float2bfloat16(acc[3][e]);
            g_uv[n128 + 64 + lane]      = __float2bfloat16(acc[4][e]);
            g_uv[n128 + 64 + lane + 32] = __float2bfloat16(acc[5][e]);
        }
        __syncwarp();
    }
}

// ---------------------------------------------------------------------------
// Kernel 2 (edge): t = u[row]+v[col]+wd*d+b1; att = sig(W2.silu(t)+b2);
// fp32 red.global.add.v4 of att*x_col into d_out[row].
// 4 edges per warp-iter; all gathers batched up front.  6 blocks/SM.
// ---------------------------------------------------------------------------
__global__ void __launch_bounds__(256, 6)
edge_kernel(const float* __restrict__ W1,   // [64][129]
            const float* __restrict__ b1,
            const float* __restrict__ W2,   // [64]
            const float* __restrict__ b2p,
            float* __restrict__ agg)        // d_out
{
    const int lane = threadIdx.x & 31;
    const int w    = threadIdx.x >> 5;
    const int hw   = lane >> 4;      // which edge of the pair
    const int li   = lane & 15;      // dim group within edge

    const float4 w2_4 = ((const float4*)W2)[li];
    const float4 b1_4 = ((const float4*)b1)[li];
    float4 wd_4;
    wd_4.x = __ldg(W1 + (size_t)(li * 4 + 0) * 129 + 128);
    wd_4.y = __ldg(W1 + (size_t)(li * 4 + 1) * 129 + 128);
    wd_4.z = __ldg(W1 + (size_t)(li * 4 + 2) * 129 + 128);
    wd_4.w = __ldg(W1 + (size_t)(li * 4 + 3) * 129 + 128);
    const float b2 = b2p[0];

    const uint2* uvp = (const uint2*)g_uv;   // 32 uint2 per node (u:0-15, v:16-31)
    const uint2* xcp = (const uint2*)g_xc;   // 16 uint2 per node

    const int warpGlobal = blockIdx.x * 8 + w;
    const int nWarps     = gridDim.x * 8;

    for (int eb = warpGlobal * 4; eb < E_EDGES; eb += nWarps * 4) {
        int4 m[2];
        m[0] = __ldg(g_ep + eb + hw);
        m[1] = __ldg(g_ep + eb + 2 + hw);

        uint2 ur[2], vr[2], xr[2];
        #pragma unroll
        for (int s = 0; s < 2; s++) {
            ur[s] = __ldg(uvp + (size_t)m[s].x * 32 + li);
            vr[s] = __ldg(uvp + (size_t)m[s].y * 32 + 16 + li);
            xr[s] = __ldg(xcp + (size_t)m[s].y * 16 + li);
        }

        #pragma unroll
        for (int s = 0; s < 2; s++) {
            const float d  = __int_as_float(m[s].z);
            const float em = __int_as_float(m[s].w);
            const float4 u4 = bf16x4_to_f4(ur[s]);
            const float4 v4 = bf16x4_to_f4(vr[s]);
            const float4 x4 = bf16x4_to_f4(xr[s]);

            float4 t;
            t.x = fmaf(d, wd_4.x, u4.x + v4.x + b1_4.x);
            t.y = fmaf(d, wd_4.y, u4.y + v4.y + b1_4.y);
            t.z = fmaf(d, wd_4.z, u4.z + v4.z + b1_4.z);
            t.w = fmaf(d, wd_4.w, u4.w + v4.w + b1_4.w);

            const float h0 = t.x * fsig_t(t.x);
            const float h1 = t.y * fsig_t(t.y);
            const float h2 = t.z * fsig_t(t.z);
            const float h3 = t.w * fsig_t(t.w);

            float p = fmaf(h0, w2_4.x,
                      fmaf(h1, w2_4.y,
                      fmaf(h2, w2_4.z, h3 * w2_4.w)));
            #pragma unroll
            for (int off = 8; off; off >>= 1)          // reduce within 16 lanes
                p += __shfl_xor_sync(0xffffffffu, p, off);

            const float att = fsig_t(p + b2) * em * NORM_INV;

            float* dst = agg + (size_t)m[s].x * 64 + li * 4;
            red_add_v4(dst, x4.x * att, x4.y * att, x4.z * att, x4.w * att);
        }
    }
}

// ---------------------------------------------------------------------------
// Kernel 3: out = silu(LN(io)).  io holds x + agg (fp32).
// 16 lanes per row (float4 per lane), 2 rows per warp. Exact sigmoid.
// ---------------------------------------------------------------------------
__global__ void ln_kernel(const float* __restrict__ g,
                          const float* __restrict__ bln,
                          float* __restrict__ io)
{
    const int lane = threadIdx.x & 31;
    const int w    = threadIdx.x >> 5;
    const int li   = lane & 15;
    const int row  = blockIdx.x * 16 + w * 2 + (lane >> 4);
    if (row >= N_NODES) return;

    float4 v = ((const float4*)io)[(size_t)row * 16 + li];

    float s = v.x + v.y + v.z + v.w;
    #pragma unroll
    for (int off = 8; off; off >>= 1)
        s += __shfl_xor_sync(0xffffffffu, s, off);
    const float mu = s * (1.0f / 64.0f);

    const float dx = v.x - mu, dy = v.y - mu, dz = v.z - mu, dw = v.w - mu;
    float q = dx * dx + dy * dy + dz * dz + dw * dw;
    #pragma unroll
    for (int off = 8; off; off >>= 1)
        q += __shfl_xor_sync(0xffffffffu, q, off);
    const float rs = rsqrtf(q * (1.0f / 64.0f) + LN_EPS);

    const float4 gg = __ldg((const float4*)g + li);
    const float4 bb = __ldg((const float4*)bln + li);
    float4 o;
    o.x = fmaf(dx * rs, gg.x, bb.x);
    o.y = fmaf(dy * rs, gg.y, bb.y);
    o.z = fmaf(dz * rs, gg.z, bb.z);
    o.w = fmaf(dw * rs, gg.w, bb.w);
    o.x *= fsig(o.x);
    o.y *= fsig(o.y);
    o.z *= fsig(o.z);
    o.w *= fsig(o.w);
    ((float4*)io)[(size_t)row * 16 + li] = o;
}

// ---------------------------------------------------------------------------
// Launch: setup(compose ∥ pack) -> prep -> edge -> layernorm.
// ---------------------------------------------------------------------------
extern "C" void kernel_launch(void* const* d_in, const int* in_sizes, int n_in,
                              void* d_out, int out_size)
{
    const float* h     = (const float*)d_in[0];
    const float* dist  = (const float*)d_in[1];
    const int*   edges = (const int*)d_in[2];   // JAX x64-disabled => int32
    /* d_in[3] node_mask: unused by the reference */
    const float* emask = (const float*)d_in[4];
    const float* Wlin  = (const float*)d_in[5];
    const float* blin  = (const float*)d_in[6];
    const float* W1    = (const float*)d_in[7];
    const float* b1    = (const float*)d_in[8];
    const float* W2    = (const float*)d_in[9];
    const float* b2    = (const float*)d_in[10];
    const float* lng   = (const float*)d_in[11];
    const float* lnb   = (const float*)d_in[12];
    float* out = (float*)d_out;

    cudaFuncSetAttribute(prep_kernel,
                         cudaFuncAttributeMaxDynamicSharedMemorySize, PREP_SMEM);

    setup_kernel<<<740, 256>>>(Wlin, blin, W1, edges, dist, emask);
    prep_kernel<<<592, 256, PREP_SMEM>>>(h, out);
    edge_kernel<<<888, 256>>>(W1, b1, W2, b2, out);      // 6 blocks/SM, 1 wave
    ln_kernel<<<(N_NODES + 15) / 16, 256>>>(lng, lnb, out);
}

// round 12
// speedup vs baseline: 1.0931x; 1.0414x over previous
#include <cuda_runtime.h>
#include <cuda_bf16.h>
#include <cstdint>
#include <cstddef>

#define N_NODES 100000
#define E_EDGES 1000000
#define D_DIM   64
#define NORM_INV 0.01f
#define LN_EPS  1e-5f

// Per-node features for the edge kernel (bf16; att path is /100-damped)
__device__ __nv_bfloat16 g_uv[(size_t)N_NODES * 128];  // [node][0:64]=u, [64:128]=v
__device__ __nv_bfloat16 g_xc[(size_t)N_NODES * 64];   // x copy (bf16)
// Stacked bf16 weights for the uv GEMM: rows 0-63 = A = W1[:,:64],
// rows 64-127 = B = W1[:,64:128]; row stride 72 (smem bank-conflict-free)
__device__ __nv_bfloat16 g_Wab[128 * 72];
// Packed per-edge metadata {row, col, dist, emask} (16 B)
__device__ int4 g_ep[(size_t)E_EDGES];

// Exact sigmoid (used output-side in LN)
__device__ __forceinline__ float fsig(float v) {
    return __fdividef(1.0f, 1.0f + __expf(-v));
}
// Fast sigmoid via HW tanh (att path; /100-damped)
__device__ __forceinline__ float fsig_t(float v) {
    float t;
    asm("tanh.approx.f32 %0, %1;" : "=f"(t) : "f"(v * 0.5f));
    return fmaf(t, 0.5f, 0.5f);
}

__device__ __forceinline__ void red_add_v4(float* dst, float a, float b,
                                           float c, float d) {
    asm volatile("red.global.add.v4.f32 [%0], {%1, %2, %3, %4};"
                 :: "l"(dst), "f"(a), "f"(b), "f"(c), "f"(d) : "memory");
}

__device__ __forceinline__ float4 bf16x4_to_f4(uint2 r) {
    const float2 a = __bfloat1622float2(*reinterpret_cast<__nv_bfloat162*>(&r.x));
    const float2 b = __bfloat1622float2(*reinterpret_cast<__nv_bfloat162*>(&r.y));
    return make_float4(a.x, a.y, b.x, b.y);
}

__device__ __forceinline__ unsigned pack_bf2(float a, float b) {
    const __nv_bfloat162 t = __float22bfloat162_rn(make_float2(a, b));
    return *reinterpret_cast<const unsigned*>(&t);
}

// ---------------------------------------------------------------------------
// Kernel 0 (setup): all blocks grid-stride the edge pack; block 0 also
// converts W1's A|B halves into the stacked bf16 weight matrix g_Wab.
// ---------------------------------------------------------------------------
__global__ void setup_kernel(const float* __restrict__ W1,
                             const int* __restrict__ edges,
                             const float* __restrict__ dist,
                             const float* __restrict__ emask)
{
    const int tid = threadIdx.x;

    if (blockIdx.x == 0) {
        for (int i = tid; i < 128 * 64; i += 256) {
            const int j = i >> 6, k = i & 63;
            const float w = (j < 64) ? W1[j * 129 + k]
                                     : W1[(j - 64) * 129 + 64 + k];
            g_Wab[j * 72 + k] = __float2bfloat16(w);
        }
    }

    const int nThreads = gridDim.x * 256;
    for (int e = blockIdx.x * 256 + tid; e < E_EDGES; e += nThreads) {
        int4 m;
        m.x = __ldg(edges + e);
        m.y = __ldg(edges + E_EDGES + e);
        m.z = __float_as_int(__ldg(dist + e));
        m.w = __float_as_int(__ldg(emask + e));
        g_ep[e] = m;
    }
}

// ---------------------------------------------------------------------------
// Kernel 1 (prep): x = Wlin @ h + blin only (exact fp32).
// 8 nodes per warp-iteration; lane owns outputs j = lane, lane+32.
// Writes d_out = x (fp32 residual) and g_xc = bf16(x).
// ---------------------------------------------------------------------------
#define PREP_SMEM ((64 * 68 + 64) * 4 + 8 * 8 * 16 * 16)   // 34,048 B

__global__ void __launch_bounds__(256, 4)
prep_kernel(const float* __restrict__ h,
            const float* __restrict__ Wlin,
            const float* __restrict__ blin,
            float* __restrict__ out_res)
{
    extern __shared__ float smem[];
    float*  sWs = smem;                    // 64*68
    float*  sbs = sWs + 64 * 68;           // 64
    float4* sH  = (float4*)(sbs + 64);     // [8 warps][8 nodes][16 f4]

    const int tid = threadIdx.x;
    for (int i = tid; i < 64 * 64; i += 256)
        sWs[(i >> 6) * 68 + (i & 63)] = Wlin[i];
    if (tid < 64) sbs[tid] = blin[tid];
    __syncthreads();

    const int lane = tid & 31;
    const int w    = tid >> 5;
    const int warpGlobal = blockIdx.x * 8 + w;
    const int nWarps     = gridDim.x * 8;

    const float4* w0p = ((const float4*)sWs) + lane * 17;
    const float4* w1p = ((const float4*)sWs) + (lane + 32) * 17;
    const float bj0 = sbs[lane], bj1 = sbs[lane + 32];
    const float4* hf4 = (const float4*)h;
    float4* sHw = sH + w * (8 * 16);

    for (int nb = warpGlobal * 8; nb < N_NODES; nb += nWarps * 8) {
        #pragma unroll
        for (int ep = 0; ep < 8; ep += 2) {
            const int e  = ep + (lane >> 4);
            const int li = lane & 15;
            sHw[e * 16 + li] = hf4[(size_t)(nb + e) * 16 + li];
        }
        __syncwarp();

        float acc0[8], acc1[8];
        #pragma unroll
        for (int e = 0; e < 8; e++) { acc0[e] = bj0; acc1[e] = bj1; }

        #pragma unroll 4
        for (int kk = 0; kk < 16; kk++) {
            const float4 a = w0p[kk], b = w1p[kk];
            #pragma unroll
            for (int e = 0; e < 8; e++) {
                const float4 xv = sHw[e * 16 + kk];   // warp-uniform broadcast
                acc0[e] = fmaf(a.x, xv.x, acc0[e]);
                acc0[e] = fmaf(a.y, xv.y, acc0[e]);
                acc0[e] = fmaf(a.z, xv.z, acc0[e]);
                acc0[e] = fmaf(a.w, xv.w, acc0[e]);
                acc1[e] = fmaf(b.x, xv.x, acc1[e]);
                acc1[e] = fmaf(b.y, xv.y, acc1[e]);
                acc1[e] = fmaf(b.z, xv.z, acc1[e]);
                acc1[e] = fmaf(b.w, xv.w, acc1[e]);
            }
        }

        #pragma unroll
        for (int e = 0; e < 8; e++) {
            const size_t n64 = (size_t)(nb + e) * 64;
            out_res[n64 + lane]      = acc0[e];
            out_res[n64 + lane + 32] = acc1[e];
            g_xc[n64 + lane]      = __float2bfloat16(acc0[e]);
            g_xc[n64 + lane + 32] = __float2bfloat16(acc1[e]);
        }
        __syncwarp();
    }
}

// ---------------------------------------------------------------------------
// Kernel 1b (uv): u||v = [A;B] @ x via bf16 tensor-core MMA
// (mma.sync.m16n8k16). One warp computes a 16-node x 128-dim tile:
// 16 n-tiles x 4 k-steps. A fragments loaded from g_xc (gmem), B from
// smem-staged g_Wab (stride 72 -> bank 4g+t, conflict-free).
// ---------------------------------------------------------------------------
__global__ void __launch_bounds__(256, 2)
uv_kernel()
{
    __shared__ __nv_bfloat16 sW[128 * 72];

    const int tid = threadIdx.x;
    for (int i = tid; i < 128 * 36; i += 256)
        ((unsigned*)sW)[i] = ((const unsigned*)g_Wab)[i];
    __syncthreads();

    const int wid  = tid >> 5;
    const int tile = blockIdx.x * 8 + wid;
    if (tile >= N_NODES / 16) return;      // 6250 tiles

    const int lane = tid & 31;
    const int g = lane >> 2;               // group id (0..7)
    const int t = lane & 3;                // thread-in-group

    const __nv_bfloat16* xrow0 = g_xc + (size_t)(tile * 16 + g) * 64;
    const __nv_bfloat16* xrow1 = xrow0 + 8 * 64;

    // A fragments for all 4 k16-steps (16 regs)
    unsigned a[4][4];
    #pragma unroll
    for (int kk = 0; kk < 4; kk++) {
        a[kk][0] = *(const unsigned*)(xrow0 + kk * 16 + 2 * t);
        a[kk][1] = *(const unsigned*)(xrow1 + kk * 16 + 2 * t);
        a[kk][2] = *(const unsigned*)(xrow0 + kk * 16 + 2 * t + 8);
        a[kk][3] = *(const unsigned*)(xrow1 + kk * 16 + 2 * t + 8);
    }

    float acc[16][4];
    #pragma unroll
    for (int nt = 0; nt < 16; nt++)
        #pragma unroll
        for (int c = 0; c < 4; c++) acc[nt][c] = 0.f;

    #pragma unroll
    for (int nt = 0; nt < 16; nt++) {
        const __nv_bfloat16* wrow = sW + (nt * 8 + g) * 72;
        #pragma unroll
        for (int kk = 0; kk < 4; kk++) {
            const unsigned b0 = *(const unsigned*)(wrow + kk * 16 + 2 * t);
            const unsigned b1 = *(const unsigned*)(wrow + kk * 16 + 2 * t + 8);
            asm volatile(
                "mma.sync.aligned.m16n8k16.row.col.f32.bf16.bf16.f32 "
                "{%0,%1,%2,%3}, {%4,%5,%6,%7}, {%8,%9}, {%0,%1,%2,%3};"
                : "+f"(acc[nt][0]), "+f"(acc[nt][1]),
                  "+f"(acc[nt][2]), "+f"(acc[nt][3])
                : "r"(a[kk][0]), "r"(a[kk][1]), "r"(a[kk][2]), "r"(a[kk][3]),
                  "r"(b0), "r"(b1));
        }
    }

    // Epilogue: D row = node, col = output dim j (0-63 u, 64-127 v)
    __nv_bfloat16* orow0 = g_uv + (size_t)(tile * 16 + g) * 128;
    __nv_bfloat16* orow1 = orow0 + 8 * 128;
    #pragma unroll
    for (int nt = 0; nt < 16; nt++) {
        *(unsigned*)(orow0 + nt * 8 + 2 * t) = pack_bf2(acc[nt][0], acc[nt][1]);
        *(unsigned*)(orow1 + nt * 8 + 2 * t) = pack_bf2(acc[nt][2], acc[nt][3]);
    }
}

// ---------------------------------------------------------------------------
// Kernel 2 (edge): t = u[row]+v[col]+wd*d+b1; att = sig(W2.silu(t)+b2);
// fp32 red.global.add.v4 of att*x_col into d_out[row].
// ---------------------------------------------------------------------------
__global__ void __launch_bounds__(256, 6)
edge_kernel(const float* __restrict__ W1,   // [64][129]
            const float* __restrict__ b1,
            const float* __restrict__ W2,   // [64]
            const float* __restrict__ b2p,
            float* __restrict__ agg)        // d_out
{
    const int lane = threadIdx.x & 31;
    const int w    = threadIdx.x >> 5;
    const int hw   = lane >> 4;      // which edge of the pair
    const int li   = lane & 15;      // dim group within edge

    const float4 w2_4 = ((const float4*)W2)[li];
    const float4 b1_4 = ((const float4*)b1)[li];
    float4 wd_4;
    wd_4.x = __ldg(W1 + (size_t)(li * 4 + 0) * 129 + 128);
    wd_4.y = __ldg(W1 + (size_t)(li * 4 + 1) * 129 + 128);
    wd_4.z = __ldg(W1 + (size_t)(li * 4 + 2) * 129 + 128);
    wd_4.w = __ldg(W1 + (size_t)(li * 4 + 3) * 129 + 128);
    const float b2 = b2p[0];

    const uint2* uvp = (const uint2*)g_uv;   // 32 uint2 per node (u:0-15, v:16-31)
    const uint2* xcp = (const uint2*)g_xc;   // 16 uint2 per node

    const int warpGlobal = blockIdx.x * 8 + w;
    const int nWarps     = gridDim.x * 8;

    for (int eb = warpGlobal * 4; eb < E_EDGES; eb += nWarps * 4) {
        int4 m[2];
        m[0] = __ldg(g_ep + eb + hw);
        m[1] = __ldg(g_ep + eb + 2 + hw);

        uint2 ur[2], vr[2], xr[2];
        #pragma unroll
        for (int s = 0; s < 2; s++) {
            ur[s] = __ldg(uvp + (size_t)m[s].x * 32 + li);
            vr[s] = __ldg(uvp + (size_t)m[s].y * 32 + 16 + li);
            xr[s] = __ldg(xcp + (size_t)m[s].y * 16 + li);
        }

        #pragma unroll
        for (int s = 0; s < 2; s++) {
            const float d  = __int_as_float(m[s].z);
            const float em = __int_as_float(m[s].w);
            const float4 u4 = bf16x4_to_f4(ur[s]);
            const float4 v4 = bf16x4_to_f4(vr[s]);
            const float4 x4 = bf16x4_to_f4(xr[s]);

            float4 t;
            t.x = fmaf(d, wd_4.x, u4.x + v4.x + b1_4.x);
            t.y = fmaf(d, wd_4.y, u4.y + v4.y + b1_4.y);
            t.z = fmaf(d, wd_4.z, u4.z + v4.z + b1_4.z);
            t.w = fmaf(d, wd_4.w, u4.w + v4.w + b1_4.w);

            const float h0 = t.x * fsig_t(t.x);
            const float h1 = t.y * fsig_t(t.y);
            const float h2 = t.z * fsig_t(t.z);
            const float h3 = t.w * fsig_t(t.w);

            float p = fmaf(h0, w2_4.x,
                      fmaf(h1, w2_4.y,
                      fmaf(h2, w2_4.z, h3 * w2_4.w)));
            #pragma unroll
            for (int off = 8; off; off >>= 1)          // reduce within 16 lanes
                p += __shfl_xor_sync(0xffffffffu, p, off);

            const float att = fsig_t(p + b2) * em * NORM_INV;

            float* dst = agg + (size_t)m[s].x * 64 + li * 4;
            red_add_v4(dst, x4.x * att, x4.y * att, x4.z * att, x4.w * att);
        }
    }
}

// ---------------------------------------------------------------------------
// Kernel 3: out = silu(LN(io)).  io holds x + agg (fp32).
// 16 lanes per row (float4 per lane), 2 rows per warp. Exact sigmoid.
// ---------------------------------------------------------------------------
__global__ void ln_kernel(const float* __restrict__ g,
                          const float* __restrict__ bln,
                          float* __restrict__ io)
{
    const int lane = threadIdx.x & 31;
    const int w    = threadIdx.x >> 5;
    const int li   = lane & 15;
    const int row  = blockIdx.x * 16 + w * 2 + (lane >> 4);
    if (row >= N_NODES) return;

    float4 v = ((const float4*)io)[(size_t)row * 16 + li];

    float s = v.x + v.y + v.z + v.w;
    #pragma unroll
    for (int off = 8; off; off >>= 1)
        s += __shfl_xor_sync(0xffffffffu, s, off);
    const float mu = s * (1.0f / 64.0f);

    const float dx = v.x - mu, dy = v.y - mu, dz = v.z - mu, dw = v.w - mu;
    float q = dx * dx + dy * dy + dz * dz + dw * dw;
    #pragma unroll
    for (int off = 8; off; off >>= 1)
        q += __shfl_xor_sync(0xffffffffu, q, off);
    const float rs = rsqrtf(q * (1.0f / 64.0f) + LN_EPS);

    const float4 gg = __ldg((const float4*)g + li);
    const float4 bb = __ldg((const float4*)bln + li);
    float4 o;
    o.x = fmaf(dx * rs, gg.x, bb.x);
    o.y = fmaf(dy * rs, gg.y, bb.y);
    o.z = fmaf(dz * rs, gg.z, bb.z);
    o.w = fmaf(dw * rs, gg.w, bb.w);
    o.x *= fsig(o.x);
    o.y *= fsig(o.y);
    o.z *= fsig(o.z);
    o.w *= fsig(o.w);
    ((float4*)io)[(size_t)row * 16 + li] = o;
}

// ---------------------------------------------------------------------------
// Launch: setup(pack + bf16 weights) -> prep(x) -> uv(MMA) -> edge -> LN.
// ---------------------------------------------------------------------------
extern "C" void kernel_launch(void* const* d_in, const int* in_sizes, int n_in,
                              void* d_out, int out_size)
{
    const float* h     = (const float*)d_in[0];
    const float* dist  = (const float*)d_in[1];
    const int*   edges = (const int*)d_in[2];   // JAX x64-disabled => int32
    /* d_in[3] node_mask: unused by the reference */
    const float* emask = (const float*)d_in[4];
    const float* Wlin  = (const float*)d_in[5];
    const float* blin  = (const float*)d_in[6];
    const float* W1    = (const float*)d_in[7];
    const float* b1    = (const float*)d_in[8];
    const float* W2    = (const float*)d_in[9];
    const float* b2    = (const float*)d_in[10];
    const float* lng   = (const float*)d_in[11];
    const float* lnb   = (const float*)d_in[12];
    float* out = (float*)d_out;

    cudaFuncSetAttribute(prep_kernel,
                         cudaFuncAttributeMaxDynamicSharedMemorySize, PREP_SMEM);

    setup_kernel<<<740, 256>>>(W1, edges, dist, emask);
    prep_kernel<<<592, 256, PREP_SMEM>>>(h, Wlin, blin, out);
    uv_kernel<<<(N_NODES / 16 + 7) / 8, 256>>>();        // 782 blocks
    edge_kernel<<<888, 256>>>(W1, b1, W2, b2, out);      // 6 blocks/SM, 1 wave
    ln_kernel<<<(N_NODES + 15) / 16, 256>>>(lng, lnb, out);
}

// round 13
// speedup vs baseline: 1.1372x; 1.0403x over previous
#include <cuda_runtime.h>
#include <cuda_bf16.h>
#include <cstdint>
#include <cstddef>

#define N_NODES 100000
#define E_EDGES 1000000
#define D_DIM   64
#define NORM_INV 0.01f
#define LN_EPS  1e-5f

// Interleaved per-node table (bf16): [0:64)=u, [64:192) = 16 groups of
// {v[4g..4g+3] , x[4g..4g+3]}  ->  u gather = uint2, v+x gather = ONE uint4.
__device__ __align__(16) __nv_bfloat16 g_uvx[(size_t)N_NODES * 192];
// Contiguous bf16 x (A-fragment source for the uv MMA kernel)
__device__ __nv_bfloat16 g_xc[(size_t)N_NODES * 64];
// Packed per-edge metadata {row, col, dist, emask} (16 B)
__device__ int4 g_ep[(size_t)E_EDGES];

// Exact sigmoid (used output-side in LN)
__device__ __forceinline__ float fsig(float v) {
    return __fdividef(1.0f, 1.0f + __expf(-v));
}
// Fast sigmoid via HW tanh (att path; /100-damped)
__device__ __forceinline__ float fsig_t(float v) {
    float t;
    asm("tanh.approx.f32 %0, %1;" : "=f"(t) : "f"(v * 0.5f));
    return fmaf(t, 0.5f, 0.5f);
}

__device__ __forceinline__ void red_add_v4(float* dst, float a, float b,
                                           float c, float d) {
    asm volatile("red.global.add.v4.f32 [%0], {%1, %2, %3, %4};"
                 :: "l"(dst), "f"(a), "f"(b), "f"(c), "f"(d) : "memory");
}

__device__ __forceinline__ float4 bf16x4_to_f4(uint2 r) {
    const float2 a = __bfloat1622float2(*reinterpret_cast<__nv_bfloat162*>(&r.x));
    const float2 b = __bfloat1622float2(*reinterpret_cast<__nv_bfloat162*>(&r.y));
    return make_float4(a.x, a.y, b.x, b.y);
}

__device__ __forceinline__ unsigned pack_bf2(float a, float b) {
    const __nv_bfloat162 t = __float22bfloat162_rn(make_float2(a, b));
    return *reinterpret_cast<const unsigned*>(&t);
}

// ---------------------------------------------------------------------------
// Kernel 0 (pack): g_ep[e] = {row, col, dist, emask}.
// ---------------------------------------------------------------------------
__global__ void pack_kernel(const int* __restrict__ edges,
                            const float* __restrict__ dist,
                            const float* __restrict__ emask)
{
    const int tid = threadIdx.x;
    const int nThreads = gridDim.x * 256;
    for (int e = blockIdx.x * 256 + tid; e < E_EDGES; e += nThreads) {
        int4 m;
        m.x = __ldg(edges + e);
        m.y = __ldg(edges + E_EDGES + e);
        m.z = __float_as_int(__ldg(dist + e));
        m.w = __float_as_int(__ldg(emask + e));
        g_ep[e] = m;
    }
}

// ---------------------------------------------------------------------------
// Kernel 1 (prep): x = Wlin @ h + blin (exact fp32).
// Writes d_out = x (fp32 residual), g_xc = bf16(x), and the interleaved
// x-slots of g_uvx (edge kernel reads v+x with one uint4).
// ---------------------------------------------------------------------------
#define PREP_SMEM ((64 * 68 + 64) * 4 + 8 * 8 * 16 * 16)   // 34,048 B

__global__ void __launch_bounds__(256, 4)
prep_kernel(const float* __restrict__ h,
            const float* __restrict__ Wlin,
            const float* __restrict__ blin,
            float* __restrict__ out_res)
{
    extern __shared__ float smem[];
    float*  sWs = smem;                    // 64*68
    float*  sbs = sWs + 64 * 68;           // 64
    float4* sH  = (float4*)(sbs + 64);     // [8 warps][8 nodes][16 f4]

    const int tid = threadIdx.x;
    for (int i = tid; i < 64 * 64; i += 256)
        sWs[(i >> 6) * 68 + (i & 63)] = Wlin[i];
    if (tid < 64) sbs[tid] = blin[tid];
    __syncthreads();

    const int lane = tid & 31;
    const int w    = tid >> 5;
    const int warpGlobal = blockIdx.x * 8 + w;
    const int nWarps     = gridDim.x * 8;

    const float4* w0p = ((const float4*)sWs) + lane * 17;
    const float4* w1p = ((const float4*)sWs) + (lane + 32) * 17;
    const float bj0 = sbs[lane], bj1 = sbs[lane + 32];
    const float4* hf4 = (const float4*)h;
    float4* sHw = sH + w * (8 * 16);

    // interleaved x-slot for dim d: 64 + (d>>2)*8 + 4 + (d&3); d+32 = +64
    const unsigned xslot = 64u + ((lane >> 2) << 3) + 4u + (lane & 3);

    for (int nb = warpGlobal * 8; nb < N_NODES; nb += nWarps * 8) {
        #pragma unroll
        for (int ep = 0; ep < 8; ep += 2) {
            const int e  = ep + (lane >> 4);
            const int li = lane & 15;
            sHw[e * 16 + li] = hf4[(size_t)(nb + e) * 16 + li];
        }
        __syncwarp();

        float acc0[8], acc1[8];
        #pragma unroll
        for (int e = 0; e < 8; e++) { acc0[e] = bj0; acc1[e] = bj1; }

        #pragma unroll 4
        for (int kk = 0; kk < 16; kk++) {
            const float4 a = w0p[kk], b = w1p[kk];
            #pragma unroll
            for (int e = 0; e < 8; e++) {
                const float4 xv = sHw[e * 16 + kk];   // warp-uniform broadcast
                acc0[e] = fmaf(a.x, xv.x, acc0[e]);
                acc0[e] = fmaf(a.y, xv.y, acc0[e]);
                acc0[e] = fmaf(a.z, xv.z, acc0[e]);
                acc0[e] = fmaf(a.w, xv.w, acc0[e]);
                acc1[e] = fmaf(b.x, xv.x, acc1[e]);
                acc1[e] = fmaf(b.y, xv.y, acc1[e]);
                acc1[e] = fmaf(b.z, xv.z, acc1[e]);
                acc1[e] = fmaf(b.w, xv.w, acc1[e]);
            }
        }

        #pragma unroll
        for (int e = 0; e < 8; e++) {
            const size_t n64  = (size_t)(nb + e) * 64;
            const size_t n192 = (size_t)(nb + e) * 192;
            out_res[n64 + lane]      = acc0[e];
            out_res[n64 + lane + 32] = acc1[e];
            const __nv_bfloat16 b0 = __float2bfloat16(acc0[e]);
            const __nv_bfloat16 b1 = __float2bfloat16(acc1[e]);
            g_xc[n64 + lane]      = b0;
            g_xc[n64 + lane + 32] = b1;
            g_uvx[n192 + xslot]      = b0;
            g_uvx[n192 + xslot + 64] = b1;
        }
        __syncwarp();
    }
}

// ---------------------------------------------------------------------------
// Kernel 1b (uv): u||v = [A;B] @ x via bf16 mma.sync.m16n8k16.
// Weights converted fp32->bf16 into smem in-kernel (stride 72 rows).
// Epilogue scatters u into [0:64) and v into the interleaved {v,x} slots
// of g_uvx.
// ---------------------------------------------------------------------------
__global__ void __launch_bounds__(256, 2)
uv_kernel(const float* __restrict__ W1)
{
    __shared__ __nv_bfloat16 sW[128 * 72];

    const int tid = threadIdx.x;
    for (int i = tid; i < 128 * 64; i += 256) {
        const int j = i >> 6, k = i & 63;
        const float w = (j < 64) ? __ldg(W1 + j * 129 + k)
                                 : __ldg(W1 + (j - 64) * 129 + 64 + k);
        sW[j * 72 + k] = __float2bfloat16(w);
    }
    __syncthreads();

    const int wid  = tid >> 5;
    const int tile = blockIdx.x * 8 + wid;
    if (tile >= N_NODES / 16) return;      // 6250 tiles

    const int lane = tid & 31;
    const int g = lane >> 2;               // group id (0..7)
    const int t = lane & 3;                // thread-in-group

    const __nv_bfloat16* xrow0 = g_xc + (size_t)(tile * 16 + g) * 64;
    const __nv_bfloat16* xrow1 = xrow0 + 8 * 64;

    // A fragments for all 4 k16-steps (16 regs)
    unsigned a[4][4];
    #pragma unroll
    for (int kk = 0; kk < 4; kk++) {
        a[kk][0] = *(const unsigned*)(xrow0 + kk * 16 + 2 * t);
        a[kk][1] = *(const unsigned*)(xrow1 + kk * 16 + 2 * t);
        a[kk][2] = *(const unsigned*)(xrow0 + kk * 16 + 2 * t + 8);
        a[kk][3] = *(const unsigned*)(xrow1 + kk * 16 + 2 * t + 8);
    }

    float acc[16][4];
    #pragma unroll
    for (int nt = 0; nt < 16; nt++)
        #pragma unroll
        for (int c = 0; c < 4; c++) acc[nt][c] = 0.f;

    #pragma unroll
    for (int nt = 0; nt < 16; nt++) {
        const __nv_bfloat16* wrow = sW + (nt * 8 + g) * 72;
        #pragma unroll
        for (int kk = 0; kk < 4; kk++) {
            const unsigned b0 = *(const unsigned*)(wrow + kk * 16 + 2 * t);
            const unsigned b1 = *(const unsigned*)(wrow + kk * 16 + 2 * t + 8);
            asm volatile(
                "mma.sync.aligned.m16n8k16.row.col.f32.bf16.bf16.f32 "
                "{%0,%1,%2,%3}, {%4,%5,%6,%7}, {%8,%9}, {%0,%1,%2,%3};"
                : "+f"(acc[nt][0]), "+f"(acc[nt][1]),
                  "+f"(acc[nt][2]), "+f"(acc[nt][3])
                : "r"(a[kk][0]), "r"(a[kk][1]), "r"(a[kk][2]), "r"(a[kk][3]),
                  "r"(b0), "r"(b1));
        }
    }

    // Epilogue into g_uvx: col<64 -> u slot = col ; col>=64 -> v slot
    __nv_bfloat16* orow0 = g_uvx + (size_t)(tile * 16 + g) * 192;
    __nv_bfloat16* orow1 = orow0 + (size_t)8 * 192;
    #pragma unroll
    for (int nt = 0; nt < 16; nt++) {
        const int col = nt * 8 + 2 * t;
        const unsigned slot = (col < 64)
            ? (unsigned)col
            : 64u + (unsigned)(((col - 64) >> 2) << 3) + (unsigned)((col - 64) & 3);
        *(unsigned*)(orow0 + slot) = pack_bf2(acc[nt][0], acc[nt][1]);
        *(unsigned*)(orow1 + slot) = pack_bf2(acc[nt][2], acc[nt][3]);
    }
}

// ---------------------------------------------------------------------------
// Kernel 2 (edge): t = u[row]+v[col]+wd*d+b1; att = sig(W2.silu(t)+b2);
// fp32 red.global.add.v4 of att*x_col into d_out[row].
// Gathers: uint2 (u[row]) + ONE uint4 (v||x of col) per edge-half-warp.
// ---------------------------------------------------------------------------
__global__ void __launch_bounds__(256, 6)
edge_kernel(const float* __restrict__ W1,   // [64][129]
            const float* __restrict__ b1,
            const float* __restrict__ W2,   // [64]
            const float* __restrict__ b2p,
            float* __restrict__ agg)        // d_out
{
    const int lane = threadIdx.x & 31;
    const int w    = threadIdx.x >> 5;
    const int hw   = lane >> 4;      // which edge of the pair
    const int li   = lane & 15;      // dim group within edge

    const float4 w2_4 = ((const float4*)W2)[li];
    const float4 b1_4 = ((const float4*)b1)[li];
    float4 wd_4;
    wd_4.x = __ldg(W1 + (size_t)(li * 4 + 0) * 129 + 128);
    wd_4.y = __ldg(W1 + (size_t)(li * 4 + 1) * 129 + 128);
    wd_4.z = __ldg(W1 + (size_t)(li * 4 + 2) * 129 + 128);
    wd_4.w = __ldg(W1 + (size_t)(li * 4 + 3) * 129 + 128);
    const float b2 = b2p[0];

    const char* uvx = (const char*)g_uvx;   // 384 B per node

    const int warpGlobal = blockIdx.x * 8 + w;
    const int nWarps     = gridDim.x * 8;

    for (int eb = warpGlobal * 4; eb < E_EDGES; eb += nWarps * 4) {
        int4 m[2];
        m[0] = __ldg(g_ep + eb + hw);
        m[1] = __ldg(g_ep + eb + 2 + hw);

        uint2 ur[2];
        uint4 vx[2];
        #pragma unroll
        for (int s = 0; s < 2; s++) {
            ur[s] = __ldg((const uint2*)(uvx + (size_t)m[s].x * 384 + li * 8));
            vx[s] = __ldg((const uint4*)(uvx + (size_t)m[s].y * 384 + 128 + li * 16));
        }

        #pragma unroll
        for (int s = 0; s < 2; s++) {
            const float d  = __int_as_float(m[s].z);
            const float em = __int_as_float(m[s].w);
            const float4 u4 = bf16x4_to_f4(ur[s]);
            const float4 v4 = bf16x4_to_f4(make_uint2(vx[s].x, vx[s].y));
            const float4 x4 = bf16x4_to_f4(make_uint2(vx[s].z, vx[s].w));

            float4 t;
            t.x = fmaf(d, wd_4.x, u4.x + v4.x + b1_4.x);
            t.y = fmaf(d, wd_4.y, u4.y + v4.y + b1_4.y);
            t.z = fmaf(d, wd_4.z, u4.z + v4.z + b1_4.z);
            t.w = fmaf(d, wd_4.w, u4.w + v4.w + b1_4.w);

            const float h0 = t.x * fsig_t(t.x);
            const float h1 = t.y * fsig_t(t.y);
            const float h2 = t.z * fsig_t(t.z);
            const float h3 = t.w * fsig_t(t.w);

            float p = fmaf(h0, w2_4.x,
                      fmaf(h1, w2_4.y,
                      fmaf(h2, w2_4.z, h3 * w2_4.w)));
            #pragma unroll
            for (int off = 8; off; off >>= 1)          // reduce within 16 lanes
                p += __shfl_xor_sync(0xffffffffu, p, off);

            const float att = fsig_t(p + b2) * em * NORM_INV;

            float* dst = agg + (size_t)m[s].x * 64 + li * 4;
            red_add_v4(dst, x4.x * att, x4.y * att, x4.z * att, x4.w * att);
        }
    }
}

// ---------------------------------------------------------------------------
// Kernel 3: out = silu(LN(io)).  io holds x + agg (fp32).
// ---------------------------------------------------------------------------
__global__ void ln_kernel(const float* __restrict__ g,
                          const float* __restrict__ bln,
                          float* __restrict__ io)
{
    const int lane = threadIdx.x & 31;
    const int w    = threadIdx.x >> 5;
    const int li   = lane & 15;
    const int row  = blockIdx.x * 16 + w * 2 + (lane >> 4);
    if (row >= N_NODES) return;

    float4 v = ((const float4*)io)[(size_t)row * 16 + li];

    float s = v.x + v.y + v.z + v.w;
    #pragma unroll
    for (int off = 8; off; off >>= 1)
        s += __shfl_xor_sync(0xffffffffu, s, off);
    const float mu = s * (1.0f / 64.0f);

    const float dx = v.x - mu, dy = v.y - mu, dz = v.z - mu, dw = v.w - mu;
    float q = dx * dx + dy * dy + dz * dz + dw * dw;
    #pragma unroll
    for (int off = 8; off; off >>= 1)
        q += __shfl_xor_sync(0xffffffffu, q, off);
    const float rs = rsqrtf(q * (1.0f / 64.0f) + LN_EPS);

    const float4 gg = __ldg((const float4*)g + li);
    const float4 bb = __ldg((const float4*)bln + li);
    float4 o;
    o.x = fmaf(dx * rs, gg.x, bb.x);
    o.y = fmaf(dy * rs, gg.y, bb.y);
    o.z = fmaf(dz * rs, gg.z, bb.z);
    o.w = fmaf(dw * rs, gg.w, bb.w);
    o.x *= fsig(o.x);
    o.y *= fsig(o.y);
    o.z *= fsig(o.z);
    o.w *= fsig(o.w);
    ((float4*)io)[(size_t)row * 16 + li] = o;
}

// ---------------------------------------------------------------------------
// Launch: pack -> prep(x) -> uv(MMA) -> edge -> LN.
// ---------------------------------------------------------------------------
extern "C" void kernel_launch(void* const* d_in, const int* in_sizes, int n_in,
                              void* d_out, int out_size)
{
    const float* h     = (const float*)d_in[0];
    const float* dist  = (const float*)d_in[1];
    const int*   edges = (const int*)d_in[2];   // JAX x64-disabled => int32
    /* d_in[3] node_mask: unused by the reference */
    const float* emask = (const float*)d_in[4];
    const float* Wlin  = (const float*)d_in[5];
    const float* blin  = (const float*)d_in[6];
    const float* W1    = (const float*)d_in[7];
    const float* b1    = (const float*)d_in[8];
    const float* W2    = (const float*)d_in[9];
    const float* b2    = (const float*)d_in[10];
    const float* lng   = (const float*)d_in[11];
    const float* lnb   = (const float*)d_in[12];
    float* out = (float*)d_out;

    cudaFuncSetAttribute(prep_kernel,
                         cudaFuncAttributeMaxDynamicSharedMemorySize, PREP_SMEM);

    pack_kernel<<<740, 256>>>(edges, dist, emask);
    prep_kernel<<<592, 256, PREP_SMEM>>>(h, Wlin, blin, out);
    uv_kernel<<<(N_NODES / 16 + 7) / 8, 256>>>(W1);      // 782 blocks
    edge_kernel<<<888, 256>>>(W1, b1, W2, b2, out);      // 6 blocks/SM, 1 wave
    ln_kernel<<<(N_NODES + 15) / 16, 256>>>(lng, lnb, out);
}

// round 14
// speedup vs baseline: 1.2514x; 1.1004x over previous
#include <cuda_runtime.h>
#include <cuda_bf16.h>
#include <cstdint>
#include <cstddef>

#define N_NODES 100000
#define E_EDGES 1000000
#define D_DIM   64
#define NORM_INV 0.01f
#define LN_EPS  1e-5f
#define N_GROUPS 1563            // ceil(100000 / 64)
#define N_TILES  6250            // 100000 / 16

// Interleaved per-node table (bf16): [0:64)=u, [64:192) = 16 groups of
// {v[4g..4g+3] , x[4g..4g+3]}  ->  u gather = uint2, v+x gather = ONE uint4.
__device__ __align__(16) __nv_bfloat16 g_uvx[(size_t)N_NODES * 192];
// Packed per-edge metadata {row*256, col*384, dist, emask} (16 B)
__device__ int4 g_ep[(size_t)E_EDGES];

// Exact sigmoid (used output-side in LN)
__device__ __forceinline__ float fsig(float v) {
    return __fdividef(1.0f, 1.0f + __expf(-v));
}
// Fast sigmoid via HW tanh (att path; /100-damped)
__device__ __forceinline__ float fsig_t(float v) {
    float t;
    asm("tanh.approx.f32 %0, %1;" : "=f"(t) : "f"(v * 0.5f));
    return fmaf(t, 0.5f, 0.5f);
}

__device__ __forceinline__ void red_add_v4(float* dst, float a, float b,
                                           float c, float d) {
    asm volatile("red.global.add.v4.f32 [%0], {%1, %2, %3, %4};"
                 :: "l"(dst), "f"(a), "f"(b), "f"(c), "f"(d) : "memory");
}

__device__ __forceinline__ float4 bf16x4_to_f4(uint2 r) {
    const float2 a = __bfloat1622float2(*reinterpret_cast<__nv_bfloat162*>(&r.x));
    const float2 b = __bfloat1622float2(*reinterpret_cast<__nv_bfloat162*>(&r.y));
    return make_float4(a.x, a.y, b.x, b.y);
}

__device__ __forceinline__ unsigned pack_bf2(float a, float b) {
    const __nv_bfloat162 t = __float22bfloat162_rn(make_float2(a, b));
    return *reinterpret_cast<const unsigned*>(&t);
}

// ---------------------------------------------------------------------------
// Kernel 0 (pack): g_ep[e] = {row*256, col*384, dist, emask} — byte offsets
// pre-scaled so the edge hot loop does no index IMADs.
// ---------------------------------------------------------------------------
__global__ void pack_kernel(const int* __restrict__ edges,
                            const float* __restrict__ dist,
                            const float* __restrict__ emask)
{
    const int tid = threadIdx.x;
    const int nThreads = gridDim.x * 256;
    for (int e = blockIdx.x * 256 + tid; e < E_EDGES; e += nThreads) {
        int4 m;
        m.x = __ldg(edges + e) << 8;                 // row * 256
        m.y = __ldg(edges + E_EDGES + e) * 384;      // col * 384
        m.z = __float_as_int(__ldg(dist + e));
        m.w = __float_as_int(__ldg(emask + e));
        g_ep[e] = m;
    }
}

// ---------------------------------------------------------------------------
// Kernel 1 (prep_uv, fused): per 64-node group,
//   phase A: x = Wlin @ h + blin (exact fp32) -> d_out, g_uvx x-slots, and
//            bf16 x staged in smem (stride-72 rows, MMA-fragment-ready);
//   phase B: u||v = [A;B] @ x via bf16 mma.sync.m16n8k16 from smem.
// Warp roles in phase B: tile tl = wid>>1 (16 nodes), half = wid&1
// (0 -> u cols 0..63, 1 -> v cols 64..127).
// ---------------------------------------------------------------------------
#define PREPUV_SMEM ((64*68 + 64) * 4 + (128*72 + 64*72) * 2 + 8*8*16*16) // 61,696 B

__global__ void __launch_bounds__(256, 3)
prep_uv_kernel(const float* __restrict__ h,
               const float* __restrict__ Wlin,
               const float* __restrict__ blin,
               const float* __restrict__ W1,
               float* __restrict__ out_res)
{
    extern __shared__ float smem[];
    float*          sWs = smem;                       // 64*68 f32
    float*          sbs = sWs + 64 * 68;              // 64 f32
    __nv_bfloat16*  sW1 = (__nv_bfloat16*)(sbs + 64); // 128*72 bf16
    __nv_bfloat16*  sXc = sW1 + 128 * 72;             // 64*72 bf16
    float4*         sH  = (float4*)(sXc + 64 * 72);   // [8 w][8 e][16 f4]

    const int tid = threadIdx.x;
    for (int i = tid; i < 64 * 64; i += 256)
        sWs[(i >> 6) * 68 + (i & 63)] = Wlin[i];
    if (tid < 64) sbs[tid] = blin[tid];
    for (int i = tid; i < 128 * 64; i += 256) {
        const int j = i >> 6, k = i & 63;
        const float wv = (j < 64) ? __ldg(W1 + j * 129 + k)
                                  : __ldg(W1 + (j - 64) * 129 + 64 + k);
        sW1[j * 72 + k] = __float2bfloat16(wv);
    }
    __syncthreads();

    const int lane = tid & 31;
    const int w    = tid >> 5;
    const int g    = lane >> 2;     // MMA group id (0..7)
    const int t    = lane & 3;      // thread-in-group

    const float4* w0p = ((const float4*)sWs) + lane * 17;
    const float4* w1p = ((const float4*)sWs) + (lane + 32) * 17;
    const float bj0 = sbs[lane], bj1 = sbs[lane + 32];
    const float4* hf4 = (const float4*)h;
    float4* sHw = sH + w * (8 * 16);

    // interleaved x-slot for dim d: 64 + (d>>2)*8 + 4 + (d&3); d+32 -> +64
    const unsigned xslot = 64u + ((lane >> 2) << 3) + 4u + (lane & 3);

    const int tl   = w >> 1;        // phase-B tile within group (0..3)
    const int half = w & 1;         // 0 -> u, 1 -> v

    for (int grp = blockIdx.x; grp < N_GROUPS; grp += gridDim.x) {
        // ---------------- Phase A: x GEMM for 8 nodes per warp -----------
        const int nb = grp * 64 + w * 8;
        if (nb < N_NODES) {
            #pragma unroll
            for (int ep = 0; ep < 8; ep += 2) {
                const int e  = ep + (lane >> 4);
                const int li = lane & 15;
                sHw[e * 16 + li] = hf4[(size_t)(nb + e) * 16 + li];
            }
            __syncwarp();

            float acc0[8], acc1[8];
            #pragma unroll
            for (int e = 0; e < 8; e++) { acc0[e] = bj0; acc1[e] = bj1; }

            #pragma unroll 4
            for (int kk = 0; kk < 16; kk++) {
                const float4 a = w0p[kk], b = w1p[kk];
                #pragma unroll
                for (int e = 0; e < 8; e++) {
                    const float4 xv = sHw[e * 16 + kk];   // broadcast
                    acc0[e] = fmaf(a.x, xv.x, acc0[e]);
                    acc0[e] = fmaf(a.y, xv.y, acc0[e]);
                    acc0[e] = fmaf(a.z, xv.z, acc0[e]);
                    acc0[e] = fmaf(a.w, xv.w, acc0[e]);
                    acc1[e] = fmaf(b.x, xv.x, acc1[e]);
                    acc1[e] = fmaf(b.y, xv.y, acc1[e]);
                    acc1[e] = fmaf(b.z, xv.z, acc1[e]);
                    acc1[e] = fmaf(b.w, xv.w, acc1[e]);
                }
            }

            #pragma unroll
            for (int e = 0; e < 8; e++) {
                const size_t n64  = (size_t)(nb + e) * 64;
                const size_t n192 = (size_t)(nb + e) * 192;
                out_res[n64 + lane]      = acc0[e];
                out_res[n64 + lane + 32] = acc1[e];
                const __nv_bfloat16 b0 = __float2bfloat16(acc0[e]);
                const __nv_bfloat16 b1 = __float2bfloat16(acc1[e]);
                g_uvx[n192 + xslot]      = b0;
                g_uvx[n192 + xslot + 64] = b1;
                const int lrow = w * 8 + e;          // local node row
                sXc[lrow * 72 + lane]      = b0;
                sXc[lrow * 72 + lane + 32] = b1;
            }
        }
        __syncthreads();

        // ---------------- Phase B: u/v MMA from smem x -------------------
        const int tile_g = grp * 4 + tl;
        if (tile_g < N_TILES) {
            const __nv_bfloat16* xrow0 = sXc + (tl * 16 + g) * 72;
            const __nv_bfloat16* xrow1 = xrow0 + 8 * 72;

            unsigned a[4][4];
            #pragma unroll
            for (int kk = 0; kk < 4; kk++) {
                a[kk][0] = *(const unsigned*)(xrow0 + kk * 16 + 2 * t);
                a[kk][1] = *(const unsigned*)(xrow1 + kk * 16 + 2 * t);
                a[kk][2] = *(const unsigned*)(xrow0 + kk * 16 + 2 * t + 8);
                a[kk][3] = *(const unsigned*)(xrow1 + kk * 16 + 2 * t + 8);
            }

            float acc[8][4];
            #pragma unroll
            for (int nt = 0; nt < 8; nt++)
                #pragma unroll
                for (int c = 0; c < 4; c++) acc[nt][c] = 0.f;

            #pragma unroll
            for (int nt = 0; nt < 8; nt++) {
                const __nv_bfloat16* wrow = sW1 + (half * 64 + nt * 8 + g) * 72;
                #pragma unroll
                for (int kk = 0; kk < 4; kk++) {
                    const unsigned b0 = *(const unsigned*)(wrow + kk * 16 + 2 * t);
                    const unsigned b1 = *(const unsigned*)(wrow + kk * 16 + 2 * t + 8);
                    asm volatile(
                        "mma.sync.aligned.m16n8k16.row.col.f32.bf16.bf16.f32 "
                        "{%0,%1,%2,%3}, {%4,%5,%6,%7}, {%8,%9}, {%0,%1,%2,%3};"
                        : "+f"(acc[nt][0]), "+f"(acc[nt][1]),
                          "+f"(acc[nt][2]), "+f"(acc[nt][3])
                        : "r"(a[kk][0]), "r"(a[kk][1]), "r"(a[kk][2]), "r"(a[kk][3]),
                          "r"(b0), "r"(b1));
                }
            }

            __nv_bfloat16* orow0 = g_uvx + (size_t)(tile_g * 16 + g) * 192;
            __nv_bfloat16* orow1 = orow0 + (size_t)8 * 192;
            #pragma unroll
            for (int nt = 0; nt < 8; nt++) {
                const int c = nt * 8 + 2 * t;         // col within half
                const unsigned slot = (half == 0)
                    ? (unsigned)c
                    : 64u + (unsigned)((c >> 2) << 3) + (unsigned)(c & 3);
                *(unsigned*)(orow0 + slot) = pack_bf2(acc[nt][0], acc[nt][1]);
                *(unsigned*)(orow1 + slot) = pack_bf2(acc[nt][2], acc[nt][3]);
            }
        }
        __syncthreads();
    }
}

// ---------------------------------------------------------------------------
// Kernel 2 (edge): t = u[row]+v[col]+wd*d+b1; att = sig(W2.silu(t)+b2);
// fp32 red.global.add.v4 of att*x_col into d_out[row].
// Metadata carries pre-scaled byte offsets (row*256, col*384).
// ---------------------------------------------------------------------------
__global__ void __launch_bounds__(256, 6)
edge_kernel(const float* __restrict__ W1,   // [64][129]
            const float* __restrict__ b1,
            const float* __restrict__ W2,   // [64]
            const float* __restrict__ b2p,
            float* __restrict__ agg)        // d_out
{
    const int lane = threadIdx.x & 31;
    const int w    = threadIdx.x >> 5;
    const int hw   = lane >> 4;      // which edge of the pair
    const int li   = lane & 15;      // dim group within edge

    const float4 w2_4 = ((const float4*)W2)[li];
    const float4 b1_4 = ((const float4*)b1)[li];
    float4 wd_4;
    wd_4.x = __ldg(W1 + (size_t)(li * 4 + 0) * 129 + 128);
    wd_4.y = __ldg(W1 + (size_t)(li * 4 + 1) * 129 + 128);
    wd_4.z = __ldg(W1 + (size_t)(li * 4 + 2) * 129 + 128);
    wd_4.w = __ldg(W1 + (size_t)(li * 4 + 3) * 129 + 128);
    const float b2 = b2p[0];

    const char* uvx  = (const char*)g_uvx;   // 384 B per node
    char*       aggc = (char*)agg;           // 256 B per node

    const int warpGlobal = blockIdx.x * 8 + w;
    const int nWarps     = gridDim.x * 8;

    for (int eb = warpGlobal * 4; eb < E_EDGES; eb += nWarps * 4) {
        int4 m[2];
        m[0] = __ldg(g_ep + eb + hw);
        m[1] = __ldg(g_ep + eb + 2 + hw);

        uint2 ur[2];
        uint4 vx[2];
        #pragma unroll
        for (int s = 0; s < 2; s++) {
            const int uoff = m[s].x + (m[s].x >> 1);       // row*384
            ur[s] = __ldg((const uint2*)(uvx + uoff + li * 8));
            vx[s] = __ldg((const uint4*)(uvx + m[s].y + 128 + li * 16));
        }

        #pragma unroll
        for (int s = 0; s < 2; s++) {
            const float d  = __int_as_float(m[s].z);
            const float em = __int_as_float(m[s].w);
            const float4 u4 = bf16x4_to_f4(ur[s]);
            const float4 v4 = bf16x4_to_f4(make_uint2(vx[s].x, vx[s].y));
            const float4 x4 = bf16x4_to_f4(make_uint2(vx[s].z, vx[s].w));

            float4 t;
            t.x = fmaf(d, wd_4.x, u4.x + v4.x + b1_4.x);
            t.y = fmaf(d, wd_4.y, u4.y + v4.y + b1_4.y);
            t.z = fmaf(d, wd_4.z, u4.z + v4.z + b1_4.z);
            t.w = fmaf(d, wd_4.w, u4.w + v4.w + b1_4.w);

            const float h0 = t.x * fsig_t(t.x);
            const float h1 = t.y * fsig_t(t.y);
            const float h2 = t.z * fsig_t(t.z);
            const float h3 = t.w * fsig_t(t.w);

            float p = fmaf(h0, w2_4.x,
                      fmaf(h1, w2_4.y,
                      fmaf(h2, w2_4.z, h3 * w2_4.w)));
            #pragma unroll
            for (int off = 8; off; off >>= 1)          // reduce within 16 lanes
                p += __shfl_xor_sync(0xffffffffu, p, off);

            const float att = fsig_t(p + b2) * em * NORM_INV;

            float* dst = (float*)(aggc + m[s].x + li * 16);
            red_add_v4(dst, x4.x * att, x4.y * att, x4.z * att, x4.w * att);
        }
    }
}

// ---------------------------------------------------------------------------
// Kernel 3: out = silu(LN(io)).  io holds x + agg (fp32).
// ---------------------------------------------------------------------------
__global__ void ln_kernel(const float* __restrict__ g,
                          const float* __restrict__ bln,
                          float* __restrict__ io)
{
    const int lane = threadIdx.x & 31;
    const int w    = threadIdx.x >> 5;
    const int li   = lane & 15;
    const int row  = blockIdx.x * 16 + w * 2 + (lane >> 4);
    if (row >= N_NODES) return;

    float4 v = ((const float4*)io)[(size_t)row * 16 + li];

    float s = v.x + v.y + v.z + v.w;
    #pragma unroll
    for (int off = 8; off; off >>= 1)
        s += __shfl_xor_sync(0xffffffffu, s, off);
    const float mu = s * (1.0f / 64.0f);

    const float dx = v.x - mu, dy = v.y - mu, dz = v.z - mu, dw = v.w - mu;
    float q = dx * dx + dy * dy + dz * dz + dw * dw;
    #pragma unroll
    for (int off = 8; off; off >>= 1)
        q += __shfl_xor_sync(0xffffffffu, q, off);
    const float rs = rsqrtf(q * (1.0f / 64.0f) + LN_EPS);

    const float4 gg = __ldg((const float4*)g + li);
    const float4 bb = __ldg((const float4*)bln + li);
    float4 o;
    o.x = fmaf(dx * rs, gg.x, bb.x);
    o.y = fmaf(dy * rs, gg.y, bb.y);
    o.z = fmaf(dz * rs, gg.z, bb.z);
    o.w = fmaf(dw * rs, gg.w, bb.w);
    o.x *= fsig(o.x);
    o.y *= fsig(o.y);
    o.z *= fsig(o.z);
    o.w *= fsig(o.w);
    ((float4*)io)[(size_t)row * 16 + li] = o;
}

// ---------------------------------------------------------------------------
// Launch: pack -> prep_uv(fused) -> edge -> LN.
// ---------------------------------------------------------------------------
extern "C" void kernel_launch(void* const* d_in, const int* in_sizes, int n_in,
                              void* d_out, int out_size)
{
    const float* h     = (const float*)d_in[0];
    const float* dist  = (const float*)d_in[1];
    const int*   edges = (const int*)d_in[2];   // JAX x64-disabled => int32
    /* d_in[3] node_mask: unused by the reference */
    const float* emask = (const float*)d_in[4];
    const float* Wlin  = (const float*)d_in[5];
    const float* blin  = (const float*)d_in[6];
    const float* W1    = (const float*)d_in[7];
    const float* b1    = (const float*)d_in[8];
    const float* W2    = (const float*)d_in[9];
    const float* b2    = (const float*)d_in[10];
    const float* lng   = (const float*)d_in[11];
    const float* lnb   = (const float*)d_in[12];
    float* out = (float*)d_out;

    cudaFuncSetAttribute(prep_uv_kernel,
                         cudaFuncAttributeMaxDynamicSharedMemorySize, PREPUV_SMEM);

    pack_kernel<<<740, 256>>>(edges, dist, emask);
    prep_uv_kernel<<<444, 256, PREPUV_SMEM>>>(h, Wlin, blin, W1, out);
    edge_kernel<<<888, 256>>>(W1, b1, W2, b2, out);      // 6 blocks/SM, 1 wave
    ln_kernel<<<(N_NODES + 15) / 16, 256>>>(lng, lnb, out);
}

// round 15
// speedup vs baseline: 1.2645x; 1.0105x over previous
#include <cuda_runtime.h>
#include <cuda_bf16.h>
#include <cstdint>
#include <cstddef>

#define N_NODES 100000
#define E_EDGES 1000000
#define D_DIM   64
#define NORM_INV 0.01f
#define LN_EPS  1e-5f
#define N_GROUPS 1563            // ceil(100000 / 64)
#define N_TILES  6250            // 100000 / 16

// Interleaved per-node table (bf16): [0:64)=u, [64:192) = 16 groups of
// {v[4g..4g+3] , x[4g..4g+3]}  ->  u gather = uint2, v+x gather = ONE uint4.
__device__ __align__(16) __nv_bfloat16 g_uvx[(size_t)N_NODES * 192];
// Packed per-edge metadata {row*256, col*384, dist, emask} (16 B)
__device__ int4 g_ep[(size_t)E_EDGES];

// Exact sigmoid (used output-side in LN)
__device__ __forceinline__ float fsig(float v) {
    return __fdividef(1.0f, 1.0f + __expf(-v));
}
// Fast sigmoid via HW tanh (att path; /100-damped)
__device__ __forceinline__ float fsig_t(float v) {
    float t;
    asm("tanh.approx.f32 %0, %1;" : "=f"(t) : "f"(v * 0.5f));
    return fmaf(t, 0.5f, 0.5f);
}

__device__ __forceinline__ void red_add_v4(float* dst, float a, float b,
                                           float c, float d) {
    asm volatile("red.global.add.v4.f32 [%0], {%1, %2, %3, %4};"
                 :: "l"(dst), "f"(a), "f"(b), "f"(c), "f"(d) : "memory");
}

__device__ __forceinline__ float4 bf16x4_to_f4(uint2 r) {
    const float2 a = __bfloat1622float2(*reinterpret_cast<__nv_bfloat162*>(&r.x));
    const float2 b = __bfloat1622float2(*reinterpret_cast<__nv_bfloat162*>(&r.y));
    return make_float4(a.x, a.y, b.x, b.y);
}

__device__ __forceinline__ unsigned pack_bf2(float a, float b) {
    const __nv_bfloat162 t = __float22bfloat162_rn(make_float2(a, b));
    return *reinterpret_cast<const unsigned*>(&t);
}

// ---------------------------------------------------------------------------
// Kernel 0 (pack): g_ep[e] = {row*256, col*384, dist, emask}.
// ---------------------------------------------------------------------------
__global__ void pack_kernel(const int* __restrict__ edges,
                            const float* __restrict__ dist,
                            const float* __restrict__ emask)
{
    const int tid = threadIdx.x;
    const int nThreads = gridDim.x * 256;
    for (int e = blockIdx.x * 256 + tid; e < E_EDGES; e += nThreads) {
        int4 m;
        m.x = __ldg(edges + e) << 8;                 // row * 256
        m.y = __ldg(edges + E_EDGES + e) * 384;      // col * 384
        m.z = __float_as_int(__ldg(dist + e));
        m.w = __float_as_int(__ldg(emask + e));
        g_ep[e] = m;
    }
}

// ---------------------------------------------------------------------------
// Kernel 1 (prep_uv, fused): per 64-node group,
//   A: stage h (f32) into sUVX rows; x = Wlin@h + blin (fp32) -> d_out;
//      bf16(x) into the x-slots of the SAME sUVX rows (h no longer needed);
//   B: u||v = [A;B] @ x via mma.sync from sUVX x-slots; u/v -> sUVX slots;
//   C: coalesced uint4 flush sUVX -> g_uvx.
// sUVX row = 200 bf16 (400 B): 4-bank skew per row -> conflict-free MMA reads.
// ---------------------------------------------------------------------------
#define PREPUV_SMEM ((64*68 + 64) * 4 + 128*72*2 + 64*200*2)   // 61,696 B

__global__ void __launch_bounds__(256, 3)
prep_uv_kernel(const float* __restrict__ h,
               const float* __restrict__ Wlin,
               const float* __restrict__ blin,
               const float* __restrict__ W1,
               float* __restrict__ out_res)
{
    extern __shared__ float smem[];
    float*          sWs  = smem;                        // 64*68 f32
    float*          sbs  = sWs + 64 * 68;               // 64 f32
    __nv_bfloat16*  sW1  = (__nv_bfloat16*)(sbs + 64);  // 128*72 bf16
    char*           sUVX = (char*)(sW1 + 128 * 72);     // 64 rows x 400 B

    const int tid = threadIdx.x;
    for (int i = tid; i < 64 * 64; i += 256)
        sWs[(i >> 6) * 68 + (i & 63)] = Wlin[i];
    if (tid < 64) sbs[tid] = blin[tid];
    for (int i = tid; i < 128 * 64; i += 256) {
        const int j = i >> 6, k = i & 63;
        const float wv = (j < 64) ? __ldg(W1 + j * 129 + k)
                                  : __ldg(W1 + (j - 64) * 129 + 64 + k);
        sW1[j * 72 + k] = __float2bfloat16(wv);
    }
    __syncthreads();

    const int lane = tid & 31;
    const int w    = tid >> 5;
    const int g    = lane >> 2;     // MMA group id (0..7)
    const int t    = lane & 3;      // thread-in-group

    const float4* w0p = ((const float4*)sWs) + lane * 17;
    const float4* w1p = ((const float4*)sWs) + (lane + 32) * 17;
    const float bj0 = sbs[lane], bj1 = sbs[lane + 32];
    const float4* hf4 = (const float4*)h;

    // interleaved x-slot (elements) for dim d=lane: 64+(d>>2)*8+4+(d&3)
    const unsigned xslotB = (64u + ((lane >> 2) << 3) + 4u + (lane & 3)) * 2u;

    const int tl   = w >> 1;        // phase-B tile within group (0..3)
    const int half = w & 1;         // 0 -> u, 1 -> v

    for (int grp = blockIdx.x; grp < N_GROUPS; grp += gridDim.x) {
        const int nb = grp * 64 + w * 8;

        // ------------- Phase A: h staging + x GEMM (8 nodes/warp) --------
        if (nb < N_NODES) {
            char* rows = sUVX + (size_t)(w * 8) * 400;   // this warp's rows
            #pragma unroll
            for (int ep = 0; ep < 8; ep += 2) {
                const int e  = ep + (lane >> 4);
                const int li = lane & 15;
                *(float4*)(rows + e * 400 + li * 16) =
                    hf4[(size_t)(nb + e) * 16 + li];
            }
            __syncwarp();

            float acc0[8], acc1[8];
            #pragma unroll
            for (int e = 0; e < 8; e++) { acc0[e] = bj0; acc1[e] = bj1; }

            #pragma unroll 4
            for (int kk = 0; kk < 16; kk++) {
                const float4 a = w0p[kk], b = w1p[kk];
                #pragma unroll
                for (int e = 0; e < 8; e++) {
                    const float4 xv = *(const float4*)(rows + e * 400 + kk * 16);
                    acc0[e] = fmaf(a.x, xv.x, acc0[e]);
                    acc0[e] = fmaf(a.y, xv.y, acc0[e]);
                    acc0[e] = fmaf(a.z, xv.z, acc0[e]);
                    acc0[e] = fmaf(a.w, xv.w, acc0[e]);
                    acc1[e] = fmaf(b.x, xv.x, acc1[e]);
                    acc1[e] = fmaf(b.y, xv.y, acc1[e]);
                    acc1[e] = fmaf(b.z, xv.z, acc1[e]);
                    acc1[e] = fmaf(b.w, xv.w, acc1[e]);
                }
            }
            __syncwarp();   // all h reads done -> rows may be overwritten

            #pragma unroll
            for (int e = 0; e < 8; e++) {
                const size_t n64 = (size_t)(nb + e) * 64;
                out_res[n64 + lane]      = acc0[e];
                out_res[n64 + lane + 32] = acc1[e];
                char* row = rows + e * 400;
                *(__nv_bfloat16*)(row + xslotB)        = __float2bfloat16(acc0[e]);
                *(__nv_bfloat16*)(row + xslotB + 128u) = __float2bfloat16(acc1[e]);
            }
        }
        __syncthreads();

        // ------------- Phase B: u/v MMA from sUVX x-slots ----------------
        const int tile_g = grp * 4 + tl;
        if (tile_g < N_TILES) {
            const char* xr0 = sUVX + (size_t)(tl * 16 + g) * 400;
            const char* xr1 = xr0 + 8 * 400;

            // x-slot byte offset for even dim d: (64+(d>>2)*8+4+(d&3))*2
            unsigned a[4][4];
            #pragma unroll
            for (int kk = 0; kk < 4; kk++) {
                const int d0 = kk * 16 + 2 * t;
                const int d1 = d0 + 8;
                const unsigned o0 = (64u + ((d0 >> 2) << 3) + 4u + (d0 & 3)) * 2u;
                const unsigned o1 = (64u + ((d1 >> 2) << 3) + 4u + (d1 & 3)) * 2u;
                a[kk][0] = *(const unsigned*)(xr0 + o0);
                a[kk][1] = *(const unsigned*)(xr1 + o0);
                a[kk][2] = *(const unsigned*)(xr0 + o1);
                a[kk][3] = *(const unsigned*)(xr1 + o1);
            }

            char* or0 = sUVX + (size_t)(tl * 16 + g) * 400;
            char* or1 = or0 + 8 * 400;

            #pragma unroll
            for (int nt = 0; nt < 8; nt++) {
                float acc[4] = {0.f, 0.f, 0.f, 0.f};
                const __nv_bfloat16* wrow = sW1 + (half * 64 + nt * 8 + g) * 72;
                #pragma unroll
                for (int kk = 0; kk < 4; kk++) {
                    const unsigned b0 = *(const unsigned*)(wrow + kk * 16 + 2 * t);
                    const unsigned b1 = *(const unsigned*)(wrow + kk * 16 + 2 * t + 8);
                    asm volatile(
                        "mma.sync.aligned.m16n8k16.row.col.f32.bf16.bf16.f32 "
                        "{%0,%1,%2,%3}, {%4,%5,%6,%7}, {%8,%9}, {%0,%1,%2,%3};"
                        : "+f"(acc[0]), "+f"(acc[1]), "+f"(acc[2]), "+f"(acc[3])
                        : "r"(a[kk][0]), "r"(a[kk][1]), "r"(a[kk][2]), "r"(a[kk][3]),
                          "r"(b0), "r"(b1));
                }
                const int c = nt * 8 + 2 * t;         // col within half (even)
                const unsigned slotB = ((half == 0)
                    ? (unsigned)c
                    : 64u + (unsigned)((c >> 2) << 3) + (unsigned)(c & 3)) * 2u;
                *(unsigned*)(or0 + slotB) = pack_bf2(acc[0], acc[1]);
                *(unsigned*)(or1 + slotB) = pack_bf2(acc[2], acc[3]);
            }
        }
        __syncthreads();

        // ------------- Phase C: coalesced flush sUVX -> g_uvx ------------
        {
            const int base = grp * 64;
            #pragma unroll
            for (int i = tid; i < 1536; i += 256) {     // 64 nodes x 24 uint4
                const int node  = i / 24;
                const int chunk = i % 24;
                if (base + node < N_NODES) {
                    const uint4 val = *(const uint4*)(sUVX + node * 400 + chunk * 16);
                    *(uint4*)((char*)g_uvx + (size_t)(base + node) * 384 + chunk * 16) = val;
                }
            }
        }
        __syncthreads();
    }
}

// ---------------------------------------------------------------------------
// Kernel 2 (edge): t = u[row]+v[col]+wd*d+b1; att = sig(W2.silu(t)+b2);
// fp32 red.global.add.v4 of att*x_col into d_out[row].
// ---------------------------------------------------------------------------
__global__ void __launch_bounds__(256, 6)
edge_kernel(const float* __restrict__ W1,   // [64][129]
            const float* __restrict__ b1,
            const float* __restrict__ W2,   // [64]
            const float* __restrict__ b2p,
            float* __restrict__ agg)        // d_out
{
    const int lane = threadIdx.x & 31;
    const int w    = threadIdx.x >> 5;
    const int hw   = lane >> 4;      // which edge of the pair
    const int li   = lane & 15;      // dim group within edge

    const float4 w2_4 = ((const float4*)W2)[li];
    const float4 b1_4 = ((const float4*)b1)[li];
    float4 wd_4;
    wd_4.x = __ldg(W1 + (size_t)(li * 4 + 0) * 129 + 128);
    wd_4.y = __ldg(W1 + (size_t)(li * 4 + 1) * 129 + 128);
    wd_4.z = __ldg(W1 + (size_t)(li * 4 + 2) * 129 + 128);
    wd_4.w = __ldg(W1 + (size_t)(li * 4 + 3) * 129 + 128);
    const float b2 = b2p[0];

    const char* uvx  = (const char*)g_uvx;   // 384 B per node
    char*       aggc = (char*)agg;           // 256 B per node

    const int warpGlobal = blockIdx.x * 8 + w;
    const int nWarps     = gridDim.x * 8;

    for (int eb = warpGlobal * 4; eb < E_EDGES; eb += nWarps * 4) {
        int4 m[2];
        m[0] = __ldg(g_ep + eb + hw);
        m[1] = __ldg(g_ep + eb + 2 + hw);

        uint2 ur[2];
        uint4 vx[2];
        #pragma unroll
        for (int s = 0; s < 2; s++) {
            const int uoff = m[s].x + (m[s].x >> 1);       // row*384
            ur[s] = __ldg((const uint2*)(uvx + uoff + li * 8));
            vx[s] = __ldg((const uint4*)(uvx + m[s].y + 128 + li * 16));
        }

        #pragma unroll
        for (int s = 0; s < 2; s++) {
            const float d  = __int_as_float(m[s].z);
            const float em = __int_as_float(m[s].w);
            const float4 u4 = bf16x4_to_f4(ur[s]);
            const float4 v4 = bf16x4_to_f4(make_uint2(vx[s].x, vx[s].y));
            const float4 x4 = bf16x4_to_f4(make_uint2(vx[s].z, vx[s].w));

            float4 t;
            t.x = fmaf(d, wd_4.x, u4.x + v4.x + b1_4.x);
            t.y = fmaf(d, wd_4.y, u4.y + v4.y + b1_4.y);
            t.z = fmaf(d, wd_4.z, u4.z + v4.z + b1_4.z);
            t.w = fmaf(d, wd_4.w, u4.w + v4.w + b1_4.w);

            const float h0 = t.x * fsig_t(t.x);
            const float h1 = t.y * fsig_t(t.y);
            const float h2 = t.z * fsig_t(t.z);
            const float h3 = t.w * fsig_t(t.w);

            float p = fmaf(h0, w2_4.x,
                      fmaf(h1, w2_4.y,
                      fmaf(h2, w2_4.z, h3 * w2_4.w)));
            #pragma unroll
            for (int off = 8; off; off >>= 1)          // reduce within 16 lanes
                p += __shfl_xor_sync(0xffffffffu, p, off);

            const float att = fsig_t(p + b2) * em * NORM_INV;

            float* dst = (float*)(aggc + m[s].x + li * 16);
            red_add_v4(dst, x4.x * att, x4.y * att, x4.z * att, x4.w * att);
        }
    }
}

// ---------------------------------------------------------------------------
// Kernel 3: out = silu(LN(io)).  io holds x + agg (fp32).
// Parallel sum / sum-of-squares reduction (independent shuffle chains).
// ---------------------------------------------------------------------------
__global__ void ln_kernel(const float* __restrict__ g,
                          const float* __restrict__ bln,
                          float* __restrict__ io)
{
    const int lane = threadIdx.x & 31;
    const int w    = threadIdx.x >> 5;
    const int li   = lane & 15;
    const int row  = blockIdx.x * 16 + w * 2 + (lane >> 4);
    if (row >= N_NODES) return;

    float4 v = ((const float4*)io)[(size_t)row * 16 + li];

    float s  = v.x + v.y + v.z + v.w;
    float sq = fmaf(v.x, v.x, fmaf(v.y, v.y, fmaf(v.z, v.z, v.w * v.w)));
    #pragma unroll
    for (int off = 8; off; off >>= 1) {
        s  += __shfl_xor_sync(0xffffffffu, s,  off);
        sq += __shfl_xor_sync(0xffffffffu, sq, off);
    }
    const float mu  = s * (1.0f / 64.0f);
    const float var = fmaf(-mu, mu, sq * (1.0f / 64.0f));
    const float rs  = rsqrtf(var + LN_EPS);

    const float dx = v.x - mu, dy = v.y - mu, dz = v.z - mu, dw = v.w - mu;
    const float4 gg = __ldg((const float4*)g + li);
    const float4 bb = __ldg((const float4*)bln + li);
    float4 o;
    o.x = fmaf(dx * rs, gg.x, bb.x);
    o.y = fmaf(dy * rs, gg.y, bb.y);
    o.z = fmaf(dz * rs, gg.z, bb.z);
    o.w = fmaf(dw * rs, gg.w, bb.w);
    o.x *= fsig(o.x);
    o.y *= fsig(o.y);
    o.z *= fsig(o.z);
    o.w *= fsig(o.w);
    ((float4*)io)[(size_t)row * 16 + li] = o;
}

// ---------------------------------------------------------------------------
// Launch: pack -> prep_uv(fused) -> edge -> LN.
// ---------------------------------------------------------------------------
extern "C" void kernel_launch(void* const* d_in, const int* in_sizes, int n_in,
                              void* d_out, int out_size)
{
    const float* h     = (const float*)d_in[0];
    const float* dist  = (const float*)d_in[1];
    const int*   edges = (const int*)d_in[2];   // JAX x64-disabled => int32
    /* d_in[3] node_mask: unused by the reference */
    const float* emask = (const float*)d_in[4];
    const float* Wlin  = (const float*)d_in[5];
    const float* blin  = (const float*)d_in[6];
    const float* W1    = (const float*)d_in[7];
    const float* b1    = (const float*)d_in[8];
    const float* W2    = (const float*)d_in[9];
    const float* b2    = (const float*)d_in[10];
    const float* lng   = (const float*)d_in[11];
    const float* lnb   = (const float*)d_in[12];
    float* out = (float*)d_out;

    cudaFuncSetAttribute(prep_uv_kernel,
                         cudaFuncAttributeMaxDynamicSharedMemorySize, PREPUV_SMEM);

    pack_kernel<<<740, 256>>>(edges, dist, emask);
    prep_uv_kernel<<<444, 256, PREPUV_SMEM>>>(h, Wlin, blin, W1, out);
    edge_kernel<<<888, 256>>>(W1, b1, W2, b2, out);      // 6 blocks/SM, 1 wave
    ln_kernel<<<(N_NODES + 15) / 16, 256>>>(lng, lnb, out);
}

// round 16
// speedup vs baseline: 1.2858x; 1.0168x over previous
#include <cuda_runtime.h>
#include <cuda_bf16.h>
#include <cstdint>
#include <cstddef>

#define N_NODES 100000
#define E_EDGES 1000000
#define D_DIM   64
#define NORM_INV 0.01f
#define LN_EPS  1e-5f
#define N_GROUPS 1563            // ceil(100000 / 64)
#define N_TILES  6250            // 100000 / 16
#define PACK_BLOCKS 260
#define PREP_BLOCKS 444

// Interleaved per-node table (bf16): [0:64)=u, [64:192) = 16 groups of
// {v[4g..4g+3] , x[4g..4g+3]}  ->  u gather = uint2, v+x gather = ONE uint4.
__device__ __align__(16) __nv_bfloat16 g_uvx[(size_t)N_NODES * 192];
// Packed per-edge metadata {row*256, col*384, dist, emask} (16 B)
__device__ int4 g_ep[(size_t)E_EDGES];

// Exact sigmoid (used output-side in LN)
__device__ __forceinline__ float fsig(float v) {
    return __fdividef(1.0f, 1.0f + __expf(-v));
}
// Fast sigmoid via HW tanh (att path; /100-damped)
__device__ __forceinline__ float fsig_t(float v) {
    float t;
    asm("tanh.approx.f32 %0, %1;" : "=f"(t) : "f"(v * 0.5f));
    return fmaf(t, 0.5f, 0.5f);
}

__device__ __forceinline__ void red_add_v4(float* dst, float a, float b,
                                           float c, float d) {
    asm volatile("red.global.add.v4.f32 [%0], {%1, %2, %3, %4};"
                 :: "l"(dst), "f"(a), "f"(b), "f"(c), "f"(d) : "memory");
}

__device__ __forceinline__ float4 bf16x4_to_f4(uint2 r) {
    const float2 a = __bfloat1622float2(*reinterpret_cast<__nv_bfloat162*>(&r.x));
    const float2 b = __bfloat1622float2(*reinterpret_cast<__nv_bfloat162*>(&r.y));
    return make_float4(a.x, a.y, b.x, b.y);
}

__device__ __forceinline__ unsigned pack_bf2(float a, float b) {
    const __nv_bfloat162 t = __float22bfloat162_rn(make_float2(a, b));
    return *reinterpret_cast<const unsigned*>(&t);
}

// ---------------------------------------------------------------------------
// Kernel 1 (fused): blocks [0, PACK_BLOCKS) pack g_ep and exit (short,
// memory-bound; they drain quickly while prep blocks stream in behind —
// CLC work-steal overlaps the two). Blocks [PACK_BLOCKS, +PREP_BLOCKS)
// run the prep_uv pipeline per 64-node group:
//   A: stage h (f32) into sUVX rows; x = Wlin@h + blin (fp32) -> d_out;
//      bf16(x) into the x-slots of the SAME sUVX rows;
//   B: u||v = [A;B] @ x via mma.sync from sUVX x-slots -> sUVX u/v slots;
//   C: coalesced uint4 flush sUVX -> g_uvx.
// sUVX row = 200 bf16 (400 B): 4-bank skew per row -> conflict-free MMA reads.
// ---------------------------------------------------------------------------
#define PREPUV_SMEM ((64*68 + 64) * 4 + 128*72*2 + 64*200*2)   // 61,696 B

__global__ void __launch_bounds__(256, 3)
prep_uv_kernel(const float* __restrict__ h,
               const float* __restrict__ Wlin,
               const float* __restrict__ blin,
               const float* __restrict__ W1,
               const int* __restrict__ edges,
               const float* __restrict__ dist,
               const float* __restrict__ emask,
               float* __restrict__ out_res)
{
    const int tid = threadIdx.x;

    // ---------------- Pack specialization (blocks 0..PACK_BLOCKS-1) ------
    if (blockIdx.x < PACK_BLOCKS) {
        const int stride = PACK_BLOCKS * 256;
        for (int e = blockIdx.x * 256 + tid; e < E_EDGES; e += stride) {
            int4 m;
            m.x = __ldg(edges + e) << 8;                 // row * 256
            m.y = __ldg(edges + E_EDGES + e) * 384;      // col * 384
            m.z = __float_as_int(__ldg(dist + e));
            m.w = __float_as_int(__ldg(emask + e));
            g_ep[e] = m;
        }
        return;
    }
    const int bid = blockIdx.x - PACK_BLOCKS;            // 0..PREP_BLOCKS-1

    extern __shared__ float smem[];
    float*          sWs  = smem;                        // 64*68 f32
    float*          sbs  = sWs + 64 * 68;               // 64 f32
    __nv_bfloat16*  sW1  = (__nv_bfloat16*)(sbs + 64);  // 128*72 bf16
    char*           sUVX = (char*)(sW1 + 128 * 72);     // 64 rows x 400 B

    for (int i = tid; i < 64 * 64; i += 256)
        sWs[(i >> 6) * 68 + (i & 63)] = Wlin[i];
    if (tid < 64) sbs[tid] = blin[tid];
    for (int i = tid; i < 128 * 64; i += 256) {
        const int j = i >> 6, k = i & 63;
        const float wv = (j < 64) ? __ldg(W1 + j * 129 + k)
                                  : __ldg(W1 + (j - 64) * 129 + 64 + k);
        sW1[j * 72 + k] = __float2bfloat16(wv);
    }
    __syncthreads();

    const int lane = tid & 31;
    const int w    = tid >> 5;
    const int g    = lane >> 2;     // MMA group id (0..7)
    const int t    = lane & 3;      // thread-in-group

    const float4* w0p = ((const float4*)sWs) + lane * 17;
    const float4* w1p = ((const float4*)sWs) + (lane + 32) * 17;
    const float bj0 = sbs[lane], bj1 = sbs[lane + 32];
    const float4* hf4 = (const float4*)h;

    // interleaved x-slot (bytes) for dim d=lane: (64+(d>>2)*8+4+(d&3))*2
    const unsigned xslotB = (64u + ((lane >> 2) << 3) + 4u + (lane & 3)) * 2u;

    const int tl   = w >> 1;        // phase-B tile within group (0..3)
    const int half = w & 1;         // 0 -> u, 1 -> v

    for (int grp = bid; grp < N_GROUPS; grp += PREP_BLOCKS) {
        const int nb = grp * 64 + w * 8;

        // ------------- Phase A: h staging + x GEMM (8 nodes/warp) --------
        if (nb < N_NODES) {
            char* rows = sUVX + (size_t)(w * 8) * 400;   // this warp's rows
            #pragma unroll
            for (int ep = 0; ep < 8; ep += 2) {
                const int e  = ep + (lane >> 4);
                const int li = lane & 15;
                *(float4*)(rows + e * 400 + li * 16) =
                    hf4[(size_t)(nb + e) * 16 + li];
            }
            __syncwarp();

            float acc0[8], acc1[8];
            #pragma unroll
            for (int e = 0; e < 8; e++) { acc0[e] = bj0; acc1[e] = bj1; }

            #pragma unroll 4
            for (int kk = 0; kk < 16; kk++) {
                const float4 a = w0p[kk], b = w1p[kk];
                #pragma unroll
                for (int e = 0; e < 8; e++) {
                    const float4 xv = *(const float4*)(rows + e * 400 + kk * 16);
                    acc0[e] = fmaf(a.x, xv.x, acc0[e]);
                    acc0[e] = fmaf(a.y, xv.y, acc0[e]);
                    acc0[e] = fmaf(a.z, xv.z, acc0[e]);
                    acc0[e] = fmaf(a.w, xv.w, acc0[e]);
                    acc1[e] = fmaf(b.x, xv.x, acc1[e]);
                    acc1[e] = fmaf(b.y, xv.y, acc1[e]);
                    acc1[e] = fmaf(b.z, xv.z, acc1[e]);
                    acc1[e] = fmaf(b.w, xv.w, acc1[e]);
                }
            }
            __syncwarp();   // all h reads done -> rows may be overwritten

            #pragma unroll
            for (int e = 0; e < 8; e++) {
                const size_t n64 = (size_t)(nb + e) * 64;
                out_res[n64 + lane]      = acc0[e];
                out_res[n64 + lane + 32] = acc1[e];
                char* row = rows + e * 400;
                *(__nv_bfloat16*)(row + xslotB)        = __float2bfloat16(acc0[e]);
                *(__nv_bfloat16*)(row + xslotB + 128u) = __float2bfloat16(acc1[e]);
            }
        }
        __syncthreads();

        // ------------- Phase B: u/v MMA from sUVX x-slots ----------------
        const int tile_g = grp * 4 + tl;
        if (tile_g < N_TILES) {
            const char* xr0 = sUVX + (size_t)(tl * 16 + g) * 400;
            const char* xr1 = xr0 + 8 * 400;

            unsigned a[4][4];
            #pragma unroll
            for (int kk = 0; kk < 4; kk++) {
                const int d0 = kk * 16 + 2 * t;
                const int d1 = d0 + 8;
                const unsigned o0 = (64u + ((d0 >> 2) << 3) + 4u + (d0 & 3)) * 2u;
                const unsigned o1 = (64u + ((d1 >> 2) << 3) + 4u + (d1 & 3)) * 2u;
                a[kk][0] = *(const unsigned*)(xr0 + o0);
                a[kk][1] = *(const unsigned*)(xr1 + o0);
                a[kk][2] = *(const unsigned*)(xr0 + o1);
                a[kk][3] = *(const unsigned*)(xr1 + o1);
            }

            char* or0 = sUVX + (size_t)(tl * 16 + g) * 400;
            char* or1 = or0 + 8 * 400;

            #pragma unroll
            for (int nt = 0; nt < 8; nt++) {
                float acc[4] = {0.f, 0.f, 0.f, 0.f};
                const __nv_bfloat16* wrow = sW1 + (half * 64 + nt * 8 + g) * 72;
                #pragma unroll
                for (int kk = 0; kk < 4; kk++) {
                    const unsigned b0 = *(const unsigned*)(wrow + kk * 16 + 2 * t);
                    const unsigned b1 = *(const unsigned*)(wrow + kk * 16 + 2 * t + 8);
                    asm volatile(
                        "mma.sync.aligned.m16n8k16.row.col.f32.bf16.bf16.f32 "
                        "{%0,%1,%2,%3}, {%4,%5,%6,%7}, {%8,%9}, {%0,%1,%2,%3};"
                        : "+f"(acc[0]), "+f"(acc[1]), "+f"(acc[2]), "+f"(acc[3])
                        : "r"(a[kk][0]), "r"(a[kk][1]), "r"(a[kk][2]), "r"(a[kk][3]),
                          "r"(b0), "r"(b1));
                }
                const int c = nt * 8 + 2 * t;         // col within half (even)
                const unsigned slotB = ((half == 0)
                    ? (unsigned)c
                    : 64u + (unsigned)((c >> 2) << 3) + (unsigned)(c & 3)) * 2u;
                *(unsigned*)(or0 + slotB) = pack_bf2(acc[0], acc[1]);
                *(unsigned*)(or1 + slotB) = pack_bf2(acc[2], acc[3]);
            }
        }
        __syncthreads();

        // ------------- Phase C: coalesced flush sUVX -> g_uvx ------------
        {
            const int base = grp * 64;
            #pragma unroll
            for (int i = tid; i < 1536; i += 256) {     // 64 nodes x 24 uint4
                const int node  = i / 24;
                const int chunk = i % 24;
                if (base + node < N_NODES) {
                    const uint4 val = *(const uint4*)(sUVX + node * 400 + chunk * 16);
                    *(uint4*)((char*)g_uvx + (size_t)(base + node) * 384 + chunk * 16) = val;
                }
            }
        }
        __syncthreads();
    }
}

// ---------------------------------------------------------------------------
// Kernel 2 (edge): t = u[row]+v[col]+wd*d+b1; att = sig(W2.silu(t)+b2);
// fp32 red.global.add.v4 of att*x_col into d_out[row].
// ---------------------------------------------------------------------------
__global__ void __launch_bounds__(256, 6)
edge_kernel(const float* __restrict__ W1,   // [64][129]
            const float* __restrict__ b1,
            const float* __restrict__ W2,   // [64]
            const float* __restrict__ b2p,
            float* __restrict__ agg)        // d_out
{
    const int lane = threadIdx.x & 31;
    const int w    = threadIdx.x >> 5;
    const int hw   = lane >> 4;      // which edge of the pair
    const int li   = lane & 15;      // dim group within edge

    const float4 w2_4 = ((const float4*)W2)[li];
    const float4 b1_4 = ((const float4*)b1)[li];
    float4 wd_4;
    wd_4.x = __ldg(W1 + (size_t)(li * 4 + 0) * 129 + 128);
    wd_4.y = __ldg(W1 + (size_t)(li * 4 + 1) * 129 + 128);
    wd_4.z = __ldg(W1 + (size_t)(li * 4 + 2) * 129 + 128);
    wd_4.w = __ldg(W1 + (size_t)(li * 4 + 3) * 129 + 128);
    const float b2 = b2p[0];

    const char* uvx  = (const char*)g_uvx;   // 384 B per node
    char*       aggc = (char*)agg;           // 256 B per node

    const int warpGlobal = blockIdx.x * 8 + w;
    const int nWarps     = gridDim.x * 8;

    for (int eb = warpGlobal * 4; eb < E_EDGES; eb += nWarps * 4) {
        int4 m[2];
        m[0] = __ldg(g_ep + eb + hw);
        m[1] = __ldg(g_ep + eb + 2 + hw);

        uint2 ur[2];
        uint4 vx[2];
        #pragma unroll
        for (int s = 0; s < 2; s++) {
            const int uoff = m[s].x + (m[s].x >> 1);       // row*384
            ur[s] = __ldg((const uint2*)(uvx + uoff + li * 8));
            vx[s] = __ldg((const uint4*)(uvx + m[s].y + 128 + li * 16));
        }

        #pragma unroll
        for (int s = 0; s < 2; s++) {
            const float d  = __int_as_float(m[s].z);
            const float em = __int_as_float(m[s].w);
            const float4 u4 = bf16x4_to_f4(ur[s]);
            const float4 v4 = bf16x4_to_f4(make_uint2(vx[s].x, vx[s].y));
            const float4 x4 = bf16x4_to_f4(make_uint2(vx[s].z, vx[s].w));

            float4 t;
            t.x = fmaf(d, wd_4.x, u4.x + v4.x + b1_4.x);
            t.y = fmaf(d, wd_4.y, u4.y + v4.y + b1_4.y);
            t.z = fmaf(d, wd_4.z, u4.z + v4.z + b1_4.z);
            t.w = fmaf(d, wd_4.w, u4.w + v4.w + b1_4.w);

            const float h0 = t.x * fsig_t(t.x);
            const float h1 = t.y * fsig_t(t.y);
            const float h2 = t.z * fsig_t(t.z);
            const float h3 = t.w * fsig_t(t.w);

            float p = fmaf(h0, w2_4.x,
                      fmaf(h1, w2_4.y,
                      fmaf(h2, w2_4.z, h3 * w2_4.w)));
            #pragma unroll
            for (int off = 8; off; off >>= 1)          // reduce within 16 lanes
                p += __shfl_xor_sync(0xffffffffu, p, off);

            const float att = fsig_t(p + b2) * em * NORM_INV;

            float* dst = (float*)(aggc + m[s].x + li * 16);
            red_add_v4(dst, x4.x * att, x4.y * att, x4.z * att, x4.w * att);
        }
    }
}

// ---------------------------------------------------------------------------
// Kernel 3: out = silu(LN(io)).  io holds x + agg (fp32).
// 8 lanes per row, 8 floats (2 x float4) per thread, 4 rows per warp.
// 3-step shuffle reduction within 8-lane groups.
// ---------------------------------------------------------------------------
__global__ void ln_kernel(const float* __restrict__ g,
                          const float* __restrict__ bln,
                          float* __restrict__ io)
{
    const int lane = threadIdx.x & 31;
    const int w    = threadIdx.x >> 5;
    const int li   = lane & 7;                    // 8 lanes per row
    const int row  = blockIdx.x * 32 + w * 4 + (lane >> 3);
    if (row >= N_NODES) return;

    float4 va = ((const float4*)io)[(size_t)row * 16 + li * 2];
    float4 vb = ((const float4*)io)[(size_t)row * 16 + li * 2 + 1];

    float s  = (va.x + va.y + va.z + va.w) + (vb.x + vb.y + vb.z + vb.w);
    float sq = fmaf(va.x, va.x, fmaf(va.y, va.y, fmaf(va.z, va.z, va.w * va.w)));
    sq = fmaf(vb.x, vb.x, fmaf(vb.y, vb.y, fmaf(vb.z, vb.z, fmaf(vb.w, vb.w, sq))));
    #pragma unroll
    for (int off = 4; off; off >>= 1) {
        s  += __shfl_xor_sync(0xffffffffu, s,  off);
        sq += __shfl_xor_sync(0xffffffffu, sq, off);
    }
    const float mu  = s * (1.0f / 64.0f);
    const float var = fmaf(-mu, mu, sq * (1.0f / 64.0f));
    const float rs  = rsqrtf(var + LN_EPS);

    const float4 ga = __ldg((const float4*)g + li * 2);
    const float4 gb = __ldg((const float4*)g + li * 2 + 1);
    const float4 ba = __ldg((const float4*)bln + li * 2);
    const float4 bb = __ldg((const float4*)bln + li * 2 + 1);

    float4 oa, ob;
    oa.x = fmaf((va.x - mu) * rs, ga.x, ba.x);
    oa.y = fmaf((va.y - mu) * rs, ga.y, ba.y);
    oa.z = fmaf((va.z - mu) * rs, ga.z, ba.z);
    oa.w = fmaf((va.w - mu) * rs, ga.w, ba.w);
    ob.x = fmaf((vb.x - mu) * rs, gb.x, bb.x);
    ob.y = fmaf((vb.y - mu) * rs, gb.y, bb.y);
    ob.z = fmaf((vb.z - mu) * rs, gb.z, bb.z);
    ob.w = fmaf((vb.w - mu) * rs, gb.w, bb.w);
    oa.x *= fsig(oa.x);  oa.y *= fsig(oa.y);
    oa.z *= fsig(oa.z);  oa.w *= fsig(oa.w);
    ob.x *= fsig(ob.x);  ob.y *= fsig(ob.y);
    ob.z *= fsig(ob.z);  ob.w *= fsig(ob.w);

    ((float4*)io)[(size_t)row * 16 + li * 2]     = oa;
    ((float4*)io)[(size_t)row * 16 + li * 2 + 1] = ob;
}

// ---------------------------------------------------------------------------
// Launch: prep_uv(pack ∥ prep, fused) -> edge -> LN.
// ---------------------------------------------------------------------------
extern "C" void kernel_launch(void* const* d_in, const int* in_sizes, int n_in,
                              void* d_out, int out_size)
{
    const float* h     = (const float*)d_in[0];
    const float* dist  = (const float*)d_in[1];
    const int*   edges = (const int*)d_in[2];   // JAX x64-disabled => int32
    /* d_in[3] node_mask: unused by the reference */
    const float* emask = (const float*)d_in[4];
    const float* Wlin  = (const float*)d_in[5];
    const float* blin  = (const float*)d_in[6];
    const float* W1    = (const float*)d_in[7];
    const float* b1    = (const float*)d_in[8];
    const float* W2    = (const float*)d_in[9];
    const float* b2    = (const float*)d_in[10];
    const float* lng   = (const float*)d_in[11];
    const float* lnb   = (const float*)d_in[12];
    float* out = (float*)d_out;

    cudaFuncSetAttribute(prep_uv_kernel,
                         cudaFuncAttributeMaxDynamicSharedMemorySize, PREPUV_SMEM);

    prep_uv_kernel<<<PACK_BLOCKS + PREP_BLOCKS, 256, PREPUV_SMEM>>>(
        h, Wlin, blin, W1, edges, dist, emask, out);
    edge_kernel<<<888, 256>>>(W1, b1, W2, b2, out);      // 6 blocks/SM, 1 wave
    ln_kernel<<<(N_NODES + 31) / 32, 256>>>(lng, lnb, out);
}